// round 15
// baseline (speedup 1.0000x reference)
#include <cuda_runtime.h>
#include <cuda_fp16.h>
#include <math.h>
#include <stdint.h>

// Dims (fixed for this problem)
#define Bz    4
#define Tl    8192
#define Ed    512
#define Hd    8
#define KDd   64
#define HDd   128
#define Cd    256
#define NCd   32
#define E2d   1024
#define Mtot  32768   // B*T

// ---------------- scratch (device globals; no runtime alloc) ----------------
__device__ __half g_q[(size_t)Mtot * Ed];
__device__ __half g_k[(size_t)Mtot * Ed];
__device__ __half g_v[(size_t)Mtot * E2d];
__device__ __half g_g[(size_t)Mtot * E2d];
__device__ __half g_act[(size_t)Mtot * E2d];
__device__ __half g_xh[(size_t)Mtot * Ed];    // fp16 x
__device__ float  g_kv[(size_t)Bz * NCd * Hd * KDd * HDd];
__device__ float  g_state[(size_t)Bz * NCd * Hd * KDd * HDd];
__device__ __half g_stateh[(size_t)Bz * NCd * Hd * KDd * HDd];  // fp16 shadow
__device__ float  g_cscale[Bz * NCd * Hd];
__device__ __half g_wt[2621440];   // fused [3072,512] + Wo [512,1024]

__device__ __forceinline__ uint32_t smem_u32(const void* p) {
    uint32_t a;
    asm("{ .reg .u64 t; cvta.to.shared.u64 t, %1; cvt.u32.u64 %0, t; }"
        : "=r"(a) : "l"(p));
    return a;
}

#define LDSM4(r0, r1, r2, r3, a)                                               \
    asm volatile("ldmatrix.sync.aligned.m8n8.x4.shared.b16 {%0,%1,%2,%3}, [%4];" \
                 : "=r"(r0), "=r"(r1), "=r"(r2), "=r"(r3) : "r"(a))

#define LDSM4T(r0, r1, r2, r3, a)                                              \
    asm volatile("ldmatrix.sync.aligned.m8n8.x4.trans.shared.b16 {%0,%1,%2,%3}, [%4];" \
                 : "=r"(r0), "=r"(r1), "=r"(r2), "=r"(r3) : "r"(a))

#define MMA_F16(c, a, b0, b1)                                                  \
    asm volatile("mma.sync.aligned.m16n8k16.row.col.f32.f16.f16.f32 "          \
                 "{%0,%1,%2,%3},{%4,%5,%6,%7},{%8,%9},{%0,%1,%2,%3};"          \
                 : "+f"((c)[0]), "+f"((c)[1]), "+f"((c)[2]), "+f"((c)[3])      \
                 : "r"((a)[0]), "r"((a)[1]), "r"((a)[2]), "r"((a)[3]),         \
                   "r"(b0), "r"(b1))

#define CP_ASYNC16(dst, src)                                                   \
    asm volatile("cp.async.cg.shared.global [%0], [%1], 16;"                   \
                 :: "r"(dst), "l"(src))
#define CP_COMMIT asm volatile("cp.async.commit_group;" ::: "memory")
#define CP_WAIT(n) asm volatile("cp.async.wait_group %0;" :: "n"(n) : "memory")

// ---------------- fused prologue: x->fp16 + all 5 weight transposes ----------
#define PRO_X_BLKS 8192
__global__ __launch_bounds__(256) void prologue_kernel(
    const float* __restrict__ x, __half* __restrict__ xh,
    const float* __restrict__ Wq, const float* __restrict__ Wk,
    const float* __restrict__ Wv, const float* __restrict__ Wg,
    const float* __restrict__ Wo, __half* __restrict__ wtf, __half* __restrict__ wto)
{
    int bx = blockIdx.x;
    int tid = threadIdx.x;
    if (bx < PRO_X_BLKS) {
        int i = bx * 512 + tid;
#pragma unroll
        for (int u = 0; u < 2; u++) {
            float4 v = ((const float4*)x)[i + u * 256];
            ((__half2*)xh)[(i + u * 256) * 2]     = __floats2half2_rn(v.x, v.y);
            ((__half2*)xh)[(i + u * 256) * 2 + 1] = __floats2half2_rn(v.z, v.w);
        }
        return;
    }
    int t = bx - PRO_X_BLKS;
    const float* W; __half* Wt; int K, N; float scale; int gx, gy;
    if (t < 256)        { W = Wq; Wt = wtf;           K = Ed;  N = Ed;  scale = 1.0f;   gx = t % 16;          gy = t / 16; }
    else if (t < 512)   { W = Wk; Wt = wtf + 262144;  K = Ed;  N = Ed;  scale = 0.125f; gx = (t - 256) % 16;  gy = (t - 256) / 16; }
    else if (t < 1024)  { W = Wv; Wt = wtf + 524288;  K = Ed;  N = E2d; scale = 1.0f;   gx = (t - 512) % 32;  gy = (t - 512) / 32; }
    else if (t < 1536)  { W = Wg; Wt = wtf + 1048576; K = Ed;  N = E2d; scale = 1.0f;   gx = (t - 1024) % 32; gy = (t - 1024) / 32; }
    else                { W = Wo; Wt = wto;           K = E2d; N = Ed;  scale = 1.0f;   gx = (t - 1536) % 16; gy = (t - 1536) / 16; }

    __shared__ float tsm[32][33];
    int n0 = gx * 32, k0 = gy * 32;
    int tx = tid & 31, ty = tid >> 5;
#pragma unroll
    for (int i = 0; i < 4; i++)
        tsm[ty + i * 8][tx] = W[(size_t)(k0 + ty + i * 8) * N + n0 + tx];
    __syncthreads();
#pragma unroll
    for (int i = 0; i < 4; i++)
        Wt[(size_t)(n0 + ty + i * 8) * K + k0 + tx] = __float2half_rn(tsm[tx][ty + i * 8] * scale);
}

// ================= GEMM core (128x128 tile, 2 CTAs/SM) ==========
#define STAGES 3
#define STG_BYTES 16384
#define GEMM_SMEM (STAGES * 2 * STG_BYTES)

#define GEMM_PREFETCH(kt, st, Kdim) do {                                       \
    int _k0 = (kt) * 64;                                                       \
    uint32_t _b = sbase + (st) * STG_BYTES;                                    \
    _Pragma("unroll")                                                          \
    for (int p = 0; p < 4; p++) {                                              \
        int row = p * 32 + ldrow;                                              \
        uint32_t sw = row * 128 + (((uint32_t)(kh * 2)) ^ ((row & 7) << 4));   \
        CP_ASYNC16(_b + sw, &A[(size_t)(rowBlk + row) * (Kdim) + _k0 + kh]);   \
        CP_ASYNC16(_b + BOFF + sw, &Bt[(size_t)(colBlk + row) * (Kdim) + _k0 + kh]); \
    }                                                                          \
    CP_COMMIT;                                                                 \
} while (0)

#define GEMM_MAINLOOP(Kdim) do {                                               \
    const int L = (Kdim) >> 6;                                                 \
    GEMM_PREFETCH(0, 0, Kdim);                                                 \
    GEMM_PREFETCH(1, 1, Kdim);                                                 \
    for (int kt = 0; kt < L; kt++) {                                           \
        CP_WAIT(STAGES - 2);                                                   \
        __syncthreads();                                                       \
        int nf = kt + STAGES - 1;                                              \
        if (nf < L) GEMM_PREFETCH(nf, nf % STAGES, Kdim);                      \
        int st = kt % STAGES;                                                  \
        uint32_t baA = sbase + st * STG_BYTES + offA;                          \
        uint32_t baB = sbase + st * STG_BYTES + BOFF + offB;                   \
        _Pragma("unroll")                                                      \
        for (int s = 0; s < 4; s++) {                                          \
            uint32_t af[4][4];                                                 \
            _Pragma("unroll")                                                  \
            for (int mi = 0; mi < 4; mi++)                                     \
                LDSM4(af[mi][0], af[mi][1], af[mi][2], af[mi][3],              \
                      (baA + mi * 2048) ^ (uint32_t)(s * 32));                 \
            uint32_t bf[8];                                                    \
            LDSM4(bf[0], bf[1], bf[2], bf[3], baB ^ (uint32_t)(s * 32));       \
            LDSM4(bf[4], bf[5], bf[6], bf[7], (baB + 2048) ^ (uint32_t)(s * 32)); \
            _Pragma("unroll")                                                  \
            for (int mi = 0; mi < 4; mi++)                                     \
                _Pragma("unroll")                                              \
                for (int ni = 0; ni < 4; ni++)                                 \
                    MMA_F16(acc[mi][ni], af[mi], bf[ni * 2], bf[ni * 2 + 1]);  \
        }                                                                      \
    }                                                                          \
} while (0)

#define GEMM_PROLOG                                                            \
    extern __shared__ float smemf[];                                           \
    uint32_t sbase = smem_u32(smemf);                                          \
    const uint32_t BOFF = STAGES * STG_BYTES;                                  \
    int tid = threadIdx.x;                                                     \
    int lane = tid & 31;                                                       \
    int w = tid >> 5;                                                          \
    int wm = w & 1;                                                            \
    int wn = w >> 1;                                                           \
    float acc[4][4][4];                                                        \
    _Pragma("unroll")                                                          \
    for (int mi = 0; mi < 4; mi++)                                             \
        _Pragma("unroll")                                                      \
        for (int ni = 0; ni < 4; ni++)                                         \
            _Pragma("unroll")                                                  \
            for (int r = 0; r < 4; r++) acc[mi][ni][r] = 0.f;                  \
    int ldrow = tid >> 3;                                                      \
    int kh = (tid & 7) * 8;                                                    \
    int rowA0 = wm * 64 + (lane & 15);                                         \
    uint32_t offA = rowA0 * 128 + (((lane >> 4) * 16) ^ ((rowA0 & 7) << 4));   \
    int nB0 = wn * 32 + (lane & 7) + ((lane & 16) ? 8 : 0);                    \
    uint32_t offB = nB0 * 128 + ((((lane >> 3) & 1) * 16) ^ ((nB0 & 7) << 4));

// ---------------- fused QKVG projection GEMM ----------------
__global__ __launch_bounds__(256) void qkvg_gemm(
    const __half* __restrict__ A, const __half* __restrict__ Bt,
    __half* __restrict__ qp, __half* __restrict__ kp,
    __half* __restrict__ vp, __half* __restrict__ gp,
    const float* __restrict__ sinp, const float* __restrict__ cosp)
{
    GEMM_PROLOG
    int rowBlk = blockIdx.y * 128;
    int colBlk = blockIdx.x * 128;

    GEMM_MAINLOOP(Ed);

    int cbk = blockIdx.x;
    __half* dst; int N2; int col0; bool rot;
    if (cbk < 4)       { dst = qp; N2 = Ed;  col0 = cbk * 128;        rot = true; }
    else if (cbk < 8)  { dst = kp; N2 = Ed;  col0 = (cbk - 4) * 128;  rot = true; }
    else if (cbk < 16) { dst = vp; N2 = E2d; col0 = (cbk - 8) * 128;  rot = false; }
    else               { dst = gp; N2 = E2d; col0 = (cbk - 16) * 128; rot = false; }

    int r0 = lane >> 2, cp = (lane & 3) * 2;
#pragma unroll
    for (int mi = 0; mi < 4; mi++) {
#pragma unroll
        for (int ni = 0; ni < 4; ni++) {
            size_t row = (size_t)(rowBlk + wm * 64 + mi * 16 + r0);
            int col = col0 + wn * 32 + ni * 8 + cp;
            float o0 = acc[mi][ni][0], o1 = acc[mi][ni][1];
            float o2 = acc[mi][ni][2], o3 = acc[mi][ni][3];
            if (rot) {
                int t = (int)(row % Tl);
                int d = col & 63;
                float2 sl = *(const float2*)&sinp[t * KDd + d];
                float2 cl = *(const float2*)&cosp[t * KDd + d];
                float2 sh = *(const float2*)&sinp[(t + 8) * KDd + d];
                float2 ch = *(const float2*)&cosp[(t + 8) * KDd + d];
                float n0 = o0 * cl.x - o1 * sl.x;
                float n1 = o1 * cl.y + o0 * sl.y;
                float n2 = o2 * ch.x - o3 * sh.x;
                float n3 = o3 * ch.y + o2 * sh.y;
                o0 = n0; o1 = n1; o2 = n2; o3 = n3;
            }
            *(__half2*)&dst[row * N2 + col] = __floats2half2_rn(o0, o1);
            *(__half2*)&dst[(row + 8) * N2 + col] = __floats2half2_rn(o2, o3);
        }
    }
}

// ---------------- output projection GEMM (fp32 out) ----------------
__global__ __launch_bounds__(256) void out_gemm(
    const __half* __restrict__ A, const __half* __restrict__ Bt,
    float* __restrict__ C)
{
    GEMM_PROLOG
    int rowBlk = blockIdx.y * 128;
    int colBlk = blockIdx.x * 128;

    GEMM_MAINLOOP(E2d);

    int r0 = lane >> 2, cp = (lane & 3) * 2;
#pragma unroll
    for (int mi = 0; mi < 4; mi++) {
#pragma unroll
        for (int ni = 0; ni < 4; ni++) {
            size_t row = (size_t)(rowBlk + wm * 64 + mi * 16 + r0);
            int col = colBlk + wn * 32 + ni * 8 + cp;
            float2 w0 = {acc[mi][ni][0], acc[mi][ni][1]};
            float2 w1 = {acc[mi][ni][2], acc[mi][ni][3]};
            *(float2*)&C[row * Ed + col] = w0;
            *(float2*)&C[(row + 8) * Ed + col] = w1;
        }
    }
}

// ---------------- kv per chunk (fp16 TC; vid folded into kr; V cp.async db) --
#define LDAh 72
#define LDVh 136
#define VBUFB (64 * LDVh * 2)
__global__ __launch_bounds__(256) void kv_kernel(const __half* __restrict__ k,
                                                 const __half* __restrict__ v,
                                                 const float* __restrict__ vid,
                                                 float* __restrict__ kv)
{
    __shared__ __half kr_s[64 * LDAh];
    __shared__ __half v_s[2 * 64 * LDVh];
    int bx = blockIdx.x;
    int h = bx % Hd;
    int n = (bx / Hd) % NCd;
    int b = bx / (Hd * NCd);
    int tid = threadIdx.x;
    int lane = tid & 31;
    int w = tid >> 5;
    int wm3 = w & 3;
    int wn3 = w >> 2;
    int qrow = lane >> 2, qcol = lane & 3;
    int j = lane >> 3, rr = lane & 7;
    uint32_t skr = smem_u32(kr_s), svv = smem_u32(v_s);
    int arow_off = rr + ((j >> 1) << 3);
    int acol = wm3 * 16 + ((j & 1) << 3);
    int brow_off = rr + ((j & 1) << 3);
    int bcol_off = (j >> 1) << 3;
    long row0 = (long)b * Tl + n * Cd;

#define KV_PREF_V(ccx, bf) do {                                                \
    int _row = tid >> 2;                                                       \
    int _ec = (tid & 3) * 32;                                                  \
    uint32_t _vd = svv + (uint32_t)(bf) * VBUFB + (uint32_t)(_row * LDVh + _ec) * 2; \
    const __half* _vsrc = &v[(row0 + (ccx) * 64 + _row) * E2d + h * HDd + _ec];\
    CP_ASYNC16(_vd, _vsrc);      CP_ASYNC16(_vd + 16, _vsrc + 8);              \
    CP_ASYNC16(_vd + 32, _vsrc + 16); CP_ASYNC16(_vd + 48, _vsrc + 24);        \
    CP_COMMIT;                                                                 \
} while (0)

    float acc[8][4];
#pragma unroll
    for (int ni = 0; ni < 8; ni++)
#pragma unroll
        for (int r = 0; r < 4; r++) acc[ni][r] = 0.f;

    KV_PREF_V(0, 0);
    for (int cc = 0; cc < 4; cc++) {
        int buf = cc & 1;
        CP_WAIT(0);
        __syncthreads();
        if (cc < 3) KV_PREF_V(cc + 1, buf ^ 1);
        {   // stage kr scaled by vid (row = c index)
            int kg = (tid & 3) * 16, row = tid >> 2;
            float vvf = vid[h * Cd + cc * 64 + row];
            __half2 vvh = __floats2half2_rn(vvf, vvf);
            const uint4* ks_ = (const uint4*)&k[(row0 + cc * 64 + row) * Ed + h * KDd + kg];
            uint4 a0 = ks_[0], a1 = ks_[1];
            __half2* p0 = (__half2*)&a0;
            __half2* p1 = (__half2*)&a1;
#pragma unroll
            for (int i = 0; i < 4; i++) { p0[i] = __hmul2(p0[i], vvh); p1[i] = __hmul2(p1[i], vvh); }
            *(uint4*)&kr_s[row * LDAh + kg] = a0;
            *(uint4*)&kr_s[row * LDAh + kg + 8] = a1;
        }
        __syncthreads();
        uint32_t svb = svv + buf * VBUFB;
#pragma unroll
        for (int ks = 0; ks < 4; ks++) {
            uint32_t a[4];
            LDSM4T(a[0], a[1], a[2], a[3],
                   skr + (uint32_t)(((ks * 16 + arow_off) * LDAh + acol) * 2));
#pragma unroll
            for (int eb = 0; eb < 4; eb++) {
                uint32_t b0, b1, b2, b3;
                LDSM4T(b0, b1, b2, b3,
                       svb + (uint32_t)(((ks * 16 + brow_off) * LDVh + wn3 * 64 + eb * 16 + bcol_off) * 2));
                MMA_F16(acc[eb * 2], a, b0, b1);
                MMA_F16(acc[eb * 2 + 1], a, b2, b3);
            }
        }
    }
#undef KV_PREF_V

    float* outp = kv + (size_t)bx * (KDd * HDd);
    int r = wm3 * 16 + qrow;
#pragma unroll
    for (int ni = 0; ni < 8; ni++) {
        int e = wn3 * 64 + ni * 8 + 2 * qcol;
        float2 o0 = {acc[ni][0], acc[ni][1]};
        float2 o1 = {acc[ni][2], acc[ni][3]};
        *(float2*)&outp[r * HDd + e] = o0;
        *(float2*)&outp[(r + 8) * HDd + e] = o1;
    }
}

// ---------------- scan (float2; writes fp32 state + fp16 shadow) ----------
__global__ void scan_kernel(const float2* __restrict__ kv,
                            const float* __restrict__ cd,
                            float2* __restrict__ state,
                            __half2* __restrict__ stateh)
{
    int idx = blockIdx.x * 256 + threadIdx.x;
    const int EQ = KDd * HDd / 2;
    int e2 = idx % EQ;
    int bh = idx / EQ;
    int h = bh % Hd, b = bh / Hd;
    float c = cd[h];
    float2 s = {0.f, 0.f};
    for (int n = 0; n < NCd; n++) {
        size_t off = ((size_t)((b * NCd + n) * Hd + h)) * EQ + e2;
        state[off] = s;
        stateh[off] = __floats2half2_rn(s.x, s.y);
        float2 kvv = kv[off];
        s.x = s.x * c + kvv.x;
        s.y = s.y * c + kvv.y;
    }
}

// ---------------- cross_scale (fp32 state) ----------------
__global__ void cscale_kernel(const float* __restrict__ state, float* __restrict__ cs)
{
    int bx = blockIdx.x;
    int e = threadIdx.x;
    const float* sp = state + (size_t)bx * (KDd * HDd);
    float s = 0.f;
#pragma unroll 8
    for (int k2 = 0; k2 < KDd; k2++) s += fabsf(sp[k2 * HDd + e]);
#pragma unroll
    for (int o = 16; o > 0; o >>= 1) s = fmaxf(s, __shfl_xor_sync(0xffffffff, s, o));
    __shared__ float wmax[4];
    if ((e & 31) == 0) wmax[e >> 5] = s;
    __syncthreads();
    if (e == 0) {
        float m = fmaxf(fmaxf(wmax[0], wmax[1]), fmaxf(wmax[2], wmax[3]));
        cs[bx] = fmaxf(m, 1.0f);
    }
}

// ---------------- fp16 TC fused attention; full cp.async pipeline ------------
#define KBUFB (64 * LDAh * 2)
#define ATTN_SMEM ((2 * 64 * LDAh + 2 * 64 * LDAh + 2 * 64 * LDVh) * 2 + (128 + 128 + 64) * 4)
__global__ __launch_bounds__(256) void attn_kernel(
    const __half* __restrict__ q, const __half* __restrict__ k,
    const __half* __restrict__ v, const __half* __restrict__ g,
    const __half* __restrict__ stateh, const float* __restrict__ cs,
    const float* __restrict__ mask, const float* __restrict__ qid,
    __half* __restrict__ act)
{
    extern __shared__ char smraw[];
    __half* qr_s = (__half*)smraw;              // 64*72
    __half* qk_s = qr_s + 64 * LDAh;            // 64*72
    __half* kr_s = qk_s + 64 * LDAh;            // 2 x 64*72
    __half* v_s  = kr_s + 2 * 64 * LDAh;        // 2 x 64*136
    float* ipart = (float*)(v_s + 2 * 64 * LDVh);
    float* rpart = ipart + 128;
    float* qid_s = rpart + 128;

    int bx = blockIdx.x;
    int cb = bx % 4;
    int h  = (bx / 4) % Hd;
    int n  = (bx / (4 * Hd)) % NCd;
    int b  = bx / (4 * Hd * NCd);
    int tid = threadIdx.x;
    int lane = tid & 31;
    int w = tid >> 5;
    int wm = w >> 1;
    int wn = w & 1;
    int qrow = lane >> 2, qcol = lane & 3;
    int j = lane >> 3, rr = lane & 7;
    int clr = wm * 16 + qrow;
    uint32_t skr = smem_u32(kr_s);
    uint32_t sv = smem_u32(v_s);
    int vrow_off = rr + ((j & 1) << 3);
    int vcol_off = (j >> 1) << 3;
    long row0 = (long)b * Tl + n * Cd;
    const __half* sph = stateh + ((size_t)((b * NCd + n) * Hd + h)) * (KDd * HDd);

#define ATTN_PREF(dcx, bf) do {                                                \
    int _row = tid >> 2;                                                       \
    int _kg = (tid & 3) * 16;                                                  \
    uint32_t _kd = skr + (uint32_t)(bf) * KBUFB + (uint32_t)(_row * LDAh + _kg) * 2; \
    const __half* _ksrc = &k[(row0 + (dcx) * 64 + _row) * Ed + h * KDd + _kg]; \
    CP_ASYNC16(_kd, _ksrc);                                                    \
    CP_ASYNC16(_kd + 16, _ksrc + 8);                                           \
    int _ec = (tid & 3) * 32;                                                  \
    uint32_t _vd = sv + (uint32_t)(bf) * VBUFB + (uint32_t)(_row * LDVh + _ec) * 2; \
    const __half* _vsrc = &v[(row0 + (dcx) * 64 + _row) * E2d + h * HDd + _ec];\
    CP_ASYNC16(_vd, _vsrc);      CP_ASYNC16(_vd + 16, _vsrc + 8);              \
    CP_ASYNC16(_vd + 32, _vsrc + 16); CP_ASYNC16(_vd + 48, _vsrc + 24);        \
    CP_COMMIT;                                                                 \
} while (0)

#define STATE_PREF(bf) do {                                                    \
    int _row = tid >> 2;                                                       \
    int _ec = (tid & 3) * 32;                                                  \
    uint32_t _vd = sv + (uint32_t)(bf) * VBUFB + (uint32_t)(_row * LDVh + _ec) * 2; \
    const __half* _ssrc = &sph[_row * HDd + _ec];                              \
    CP_ASYNC16(_vd, _ssrc);      CP_ASYNC16(_vd + 16, _ssrc + 8);              \
    CP_ASYNC16(_vd + 32, _ssrc + 16); CP_ASYNC16(_vd + 48, _ssrc + 24);        \
    CP_COMMIT;                                                                 \
} while (0)

    {
        int kg = (tid & 3) * 16, row = tid >> 2;
        const uint4* src = (const uint4*)&q[(row0 + cb * 64 + row) * Ed + h * KDd + kg];
        *(uint4*)&qr_s[row * LDAh + kg] = src[0];
        *(uint4*)&qr_s[row * LDAh + kg + 8] = src[1];
        if (tid < 64) qid_s[tid] = qid[h * Cd + cb * 64 + tid];
    }
    ATTN_PREF(0, 0);

    const float* mrow = mask + ((size_t)h * Cd + cb * 64) * Cd;
    float rs_lo = 0.f, rs_hi = 0.f;
    float acc2[8][4];
#pragma unroll
    for (int ni = 0; ni < 8; ni++)
#pragma unroll
        for (int r = 0; r < 4; r++) acc2[ni][r] = 0.f;

    for (int dc = 0; dc <= cb; dc++) {   // causal skip
        int buf = dc & 1;
        CP_WAIT(0);
        __syncthreads();
        if (dc < cb) ATTN_PREF(dc + 1, buf ^ 1);
        else         STATE_PREF(buf ^ 1);   // last chunk: prefetch state into idle buffer
        const __half* krb = kr_s + buf * (64 * LDAh);
        uint32_t svb = sv + buf * VBUFB;

        // qk = qr @ kr^T (warp: 16 rows x 32 keys, K=64)
        float acc1[4][4];
#pragma unroll
        for (int ni = 0; ni < 4; ni++)
#pragma unroll
            for (int r = 0; r < 4; r++) acc1[ni][r] = 0.f;
#pragma unroll
        for (int ks = 0; ks < 4; ks++) {
            int kk = ks * 16 + 2 * qcol;
            uint32_t a[4];
            a[0] = *(const uint32_t*)&qr_s[clr * LDAh + kk];
            a[1] = *(const uint32_t*)&qr_s[(clr + 8) * LDAh + kk];
            a[2] = *(const uint32_t*)&qr_s[clr * LDAh + kk + 8];
            a[3] = *(const uint32_t*)&qr_s[(clr + 8) * LDAh + kk + 8];
#pragma unroll
            for (int ni = 0; ni < 4; ni++) {
                int br = wn * 32 + ni * 8 + qrow;
                uint32_t b0 = *(const uint32_t*)&krb[br * LDAh + kk];
                uint32_t b1 = *(const uint32_t*)&krb[br * LDAh + kk + 8];
                MMA_F16(acc1[ni], a, b0, b1);
            }
        }

        // mask, |.| row-sum, stage masked qk as fp16
#pragma unroll
        for (int ni = 0; ni < 4; ni++) {
            int dl = wn * 32 + ni * 8 + 2 * qcol;
            int d = dc * 64 + dl;
            float2 mlo = *(const float2*)&mrow[(size_t)clr * Cd + d];
            float2 mhi = *(const float2*)&mrow[(size_t)(clr + 8) * Cd + d];
            acc1[ni][0] *= mlo.x; acc1[ni][1] *= mlo.y;
            acc1[ni][2] *= mhi.x; acc1[ni][3] *= mhi.y;
            rs_lo += fabsf(acc1[ni][0]) + fabsf(acc1[ni][1]);
            rs_hi += fabsf(acc1[ni][2]) + fabsf(acc1[ni][3]);
            *(__half2*)&qk_s[clr * LDAh + dl] = __floats2half2_rn(acc1[ni][0], acc1[ni][1]);
            *(__half2*)&qk_s[(clr + 8) * LDAh + dl] = __floats2half2_rn(acc1[ni][2], acc1[ni][3]);
        }
        __syncthreads();

        // PV: acc2 += qk[16x64] @ V[64 x 128-half]
#pragma unroll
        for (int ks = 0; ks < 4; ks++) {
            int kk = ks * 16 + 2 * qcol;
            uint32_t a[4];
            a[0] = *(const uint32_t*)&qk_s[clr * LDAh + kk];
            a[1] = *(const uint32_t*)&qk_s[(clr + 8) * LDAh + kk];
            a[2] = *(const uint32_t*)&qk_s[clr * LDAh + kk + 8];
            a[3] = *(const uint32_t*)&qk_s[(clr + 8) * LDAh + kk + 8];
#pragma unroll
            for (int eb = 0; eb < 4; eb++) {
                int e0 = wn * 64 + eb * 16;
                uint32_t b0, b1, b2, b3;
                LDSM4T(b0, b1, b2, b3,
                       svb + (uint32_t)(((ks * 16 + vrow_off) * LDVh + e0 + vcol_off) * 2));
                MMA_F16(acc2[eb * 2], a, b0, b1);
                MMA_F16(acc2[eb * 2 + 1], a, b2, b3);
            }
        }
    }
#undef ATTN_PREF

    // cross: state already prefetched (fp16) into buffer (cb&1)^1
    CP_WAIT(0);
    __syncthreads();
    uint32_t svs = sv + ((cb & 1) ^ 1) * VBUFB;

    float acc3[8][4];
#pragma unroll
    for (int ni = 0; ni < 8; ni++)
#pragma unroll
        for (int r = 0; r < 4; r++) acc3[ni][r] = 0.f;
#pragma unroll
    for (int ks = 0; ks < 4; ks++) {
        int kk = ks * 16 + 2 * qcol;
        uint32_t a[4];
        a[0] = *(const uint32_t*)&qr_s[clr * LDAh + kk];
        a[1] = *(const uint32_t*)&qr_s[(clr + 8) * LDAh + kk];
        a[2] = *(const uint32_t*)&qr_s[clr * LDAh + kk + 8];
        a[3] = *(const uint32_t*)&qr_s[(clr + 8) * LDAh + kk + 8];
#pragma unroll
        for (int eb = 0; eb < 4; eb++) {
            int e0 = wn * 64 + eb * 16;
            uint32_t b0, b1, b2, b3;
            LDSM4T(b0, b1, b2, b3,
                   svs + (uint32_t)(((ks * 16 + vrow_off) * LDVh + e0 + vcol_off) * 2));
            MMA_F16(acc3[eb * 2], a, b0, b1);
            MMA_F16(acc3[eb * 2 + 1], a, b2, b3);
        }
    }

    rs_lo += __shfl_xor_sync(0xffffffff, rs_lo, 1);
    rs_lo += __shfl_xor_sync(0xffffffff, rs_lo, 2);
    rs_hi += __shfl_xor_sync(0xffffffff, rs_hi, 1);
    rs_hi += __shfl_xor_sync(0xffffffff, rs_hi, 2);
    if ((lane & 3) == 0) {
        ipart[wn * 64 + clr] = rs_lo;
        ipart[wn * 64 + clr + 8] = rs_hi;
    }
    __syncthreads();

    float csc = cs[(b * NCd + n) * Hd + h];
    float is_lo = fmaxf(1.f, ipart[clr] + ipart[64 + clr]);
    float is_hi = fmaxf(1.f, ipart[clr + 8] + ipart[64 + clr + 8]);
    float inv_lo = 1.f / fmaxf(is_lo, csc);
    float inv_hi = 1.f / fmaxf(is_hi, csc);
    float qd_lo = qid_s[clr], qd_hi = qid_s[clr + 8];

    float ss_lo = 0.f, ss_hi = 0.f;
#pragma unroll
    for (int ni = 0; ni < 8; ni++) {
        acc2[ni][0] = (acc2[ni][0] + qd_lo * acc3[ni][0]) * inv_lo;
        acc2[ni][1] = (acc2[ni][1] + qd_lo * acc3[ni][1]) * inv_lo;
        acc2[ni][2] = (acc2[ni][2] + qd_hi * acc3[ni][2]) * inv_hi;
        acc2[ni][3] = (acc2[ni][3] + qd_hi * acc3[ni][3]) * inv_hi;
        ss_lo += acc2[ni][0] * acc2[ni][0] + acc2[ni][1] * acc2[ni][1];
        ss_hi += acc2[ni][2] * acc2[ni][2] + acc2[ni][3] * acc2[ni][3];
    }
    ss_lo += __shfl_xor_sync(0xffffffff, ss_lo, 1);
    ss_lo += __shfl_xor_sync(0xffffffff, ss_lo, 2);
    ss_hi += __shfl_xor_sync(0xffffffff, ss_hi, 1);
    ss_hi += __shfl_xor_sync(0xffffffff, ss_hi, 2);
    if ((lane & 3) == 0) {
        rpart[wn * 64 + clr] = ss_lo;
        rpart[wn * 64 + clr + 8] = ss_hi;
    }
    __syncthreads();

    float rn_lo = rsqrtf((rpart[clr] + rpart[64 + clr]) * (1.f / 128.f) + 1e-6f);
    float rn_hi = rsqrtf((rpart[clr + 8] + rpart[64 + clr + 8]) * (1.f / 128.f) + 1e-6f);

    long grow_lo = row0 + cb * 64 + clr;
    long grow_hi = grow_lo + 8;
#pragma unroll
    for (int ni = 0; ni < 8; ni++) {
        int e = wn * 64 + ni * 8 + 2 * qcol;
        float2 gl = __half22float2(*(const __half2*)&g[grow_lo * E2d + h * HDd + e]);
        float2 gh = __half22float2(*(const __half2*)&g[grow_hi * E2d + h * HDd + e]);
        float o0 = acc2[ni][0] * rn_lo * gl.x * __fdividef(1.f, 1.f + __expf(-gl.x));
        float o1 = acc2[ni][1] * rn_lo * gl.y * __fdividef(1.f, 1.f + __expf(-gl.y));
        float o2 = acc2[ni][2] * rn_hi * gh.x * __fdividef(1.f, 1.f + __expf(-gh.x));
        float o3 = acc2[ni][3] * rn_hi * gh.y * __fdividef(1.f, 1.f + __expf(-gh.y));
        *(__half2*)&act[grow_lo * E2d + h * HDd + e] = __floats2half2_rn(o0, o1);
        *(__half2*)&act[grow_hi * E2d + h * HDd + e] = __floats2half2_rn(o2, o3);
    }
}

// ---------------- host launch ----------------
extern "C" void kernel_launch(void* const* d_in, const int* in_sizes, int n_in,
                              void* d_out, int out_size)
{
    const float* x    = (const float*)d_in[0];
    const float* sinp = (const float*)d_in[1];
    const float* cosp = (const float*)d_in[2];
    const float* mask = (const float*)d_in[3];
    const float* cdec = (const float*)d_in[4];
    const float* qid  = (const float*)d_in[5];
    const float* vid  = (const float*)d_in[6];
    const float* Wq   = (const float*)d_in[7];
    const float* Wk   = (const float*)d_in[8];
    const float* Wv   = (const float*)d_in[9];
    const float* Wg   = (const float*)d_in[10];
    const float* Wo   = (const float*)d_in[11];
    float* out = (float*)d_out;

    float *p_kv, *p_state, *p_cs;
    __half *p_q, *p_k, *p_v, *p_g, *p_xh, *p_act, *p_wt, *p_sh;
    cudaGetSymbolAddress((void**)&p_q, g_q);
    cudaGetSymbolAddress((void**)&p_k, g_k);
    cudaGetSymbolAddress((void**)&p_v, g_v);
    cudaGetSymbolAddress((void**)&p_g, g_g);
    cudaGetSymbolAddress((void**)&p_act, g_act);
    cudaGetSymbolAddress((void**)&p_xh, g_xh);
    cudaGetSymbolAddress((void**)&p_kv, g_kv);
    cudaGetSymbolAddress((void**)&p_state, g_state);
    cudaGetSymbolAddress((void**)&p_sh, g_stateh);
    cudaGetSymbolAddress((void**)&p_cs, g_cscale);
    cudaGetSymbolAddress((void**)&p_wt, g_wt);

    __half* wtf = p_wt;
    __half* wto = p_wt + 1572864;

    cudaFuncSetAttribute(attn_kernel, cudaFuncAttributeMaxDynamicSharedMemorySize, ATTN_SMEM);
    cudaFuncSetAttribute(qkvg_gemm, cudaFuncAttributeMaxDynamicSharedMemorySize, GEMM_SMEM);
    cudaFuncSetAttribute(out_gemm, cudaFuncAttributeMaxDynamicSharedMemorySize, GEMM_SMEM);

    // fused prologue
    prologue_kernel<<<PRO_X_BLKS + 2048, 256>>>(x, p_xh, Wq, Wk, Wv, Wg, Wo, wtf, wto);

    // fused QKVG projection (rotary fused for q/k blocks)
    qkvg_gemm<<<dim3(24, 256), 256, GEMM_SMEM>>>(p_xh, wtf, p_q, p_k, p_v, p_g, sinp, cosp);

    // per-chunk kv (cp.async V), scan (fp32 + fp16 state), cross scale
    kv_kernel<<<Bz * NCd * Hd, 256>>>(p_k, p_v, vid, p_kv);
    scan_kernel<<<(Bz * Hd * KDd * HDd / 2) / 256, 256>>>(
        (const float2*)p_kv, cdec, (float2*)p_state, (__half2*)p_sh);
    cscale_kernel<<<Bz * NCd * Hd, 128>>>(p_state, p_cs);

    // fp16 tensor-core fused attention (causal skip + full cp.async pipeline)
    attn_kernel<<<Bz * NCd * Hd * 4, 256, ATTN_SMEM>>>(
        p_q, p_k, p_v, p_g, p_sh, p_cs, mask, qid, p_act);

    // output projection (fp32 out)
    out_gemm<<<dim3(4, 256), 256, GEMM_SMEM>>>(p_act, wto, out);
}

// round 16
// speedup vs baseline: 1.4513x; 1.4513x over previous
#include <cuda_runtime.h>
#include <cuda_fp16.h>
#include <math.h>
#include <stdint.h>

// Dims (fixed for this problem)
#define Bz    4
#define Tl    8192
#define Ed    512
#define Hd    8
#define KDd   64
#define HDd   128
#define Cd    256
#define NCd   32
#define E2d   1024
#define Mtot  32768   // B*T

// ---------------- scratch (device globals; no runtime alloc) ----------------
__device__ __half g_q[(size_t)Mtot * Ed];
__device__ __half g_k[(size_t)Mtot * Ed];
__device__ __half g_v[(size_t)Mtot * E2d];
__device__ __half g_g[(size_t)Mtot * E2d];
__device__ __half g_act[(size_t)Mtot * E2d];
__device__ __half g_xh[(size_t)Mtot * Ed];    // fp16 x
__device__ float  g_kv[(size_t)Bz * NCd * Hd * KDd * HDd];
__device__ float  g_state[(size_t)Bz * NCd * Hd * KDd * HDd];
__device__ float  g_cscale[Bz * NCd * Hd];
__device__ __half g_wt[2621440];   // fused [3072,512] + Wo [512,1024]

__device__ __forceinline__ uint32_t smem_u32(const void* p) {
    uint32_t a;
    asm("{ .reg .u64 t; cvta.to.shared.u64 t, %1; cvt.u32.u64 %0, t; }"
        : "=r"(a) : "l"(p));
    return a;
}

#define LDSM4(r0, r1, r2, r3, a)                                               \
    asm volatile("ldmatrix.sync.aligned.m8n8.x4.shared.b16 {%0,%1,%2,%3}, [%4];" \
                 : "=r"(r0), "=r"(r1), "=r"(r2), "=r"(r3) : "r"(a))

#define LDSM4T(r0, r1, r2, r3, a)                                              \
    asm volatile("ldmatrix.sync.aligned.m8n8.x4.trans.shared.b16 {%0,%1,%2,%3}, [%4];" \
                 : "=r"(r0), "=r"(r1), "=r"(r2), "=r"(r3) : "r"(a))

#define MMA_F16(c, a, b0, b1)                                                  \
    asm volatile("mma.sync.aligned.m16n8k16.row.col.f32.f16.f16.f32 "          \
                 "{%0,%1,%2,%3},{%4,%5,%6,%7},{%8,%9},{%0,%1,%2,%3};"          \
                 : "+f"((c)[0]), "+f"((c)[1]), "+f"((c)[2]), "+f"((c)[3])      \
                 : "r"((a)[0]), "r"((a)[1]), "r"((a)[2]), "r"((a)[3]),         \
                   "r"(b0), "r"(b1))

#define CP_ASYNC16(dst, src)                                                   \
    asm volatile("cp.async.cg.shared.global [%0], [%1], 16;"                   \
                 :: "r"(dst), "l"(src))
#define CP_COMMIT asm volatile("cp.async.commit_group;" ::: "memory")
#define CP_WAIT(n) asm volatile("cp.async.wait_group %0;" :: "n"(n) : "memory")

// ---------------- fused prologue: x->fp16 + all 5 weight transposes ----------
#define PRO_X_BLKS 8192
__global__ __launch_bounds__(256) void prologue_kernel(
    const float* __restrict__ x, __half* __restrict__ xh,
    const float* __restrict__ Wq, const float* __restrict__ Wk,
    const float* __restrict__ Wv, const float* __restrict__ Wg,
    const float* __restrict__ Wo, __half* __restrict__ wtf, __half* __restrict__ wto)
{
    int bx = blockIdx.x;
    int tid = threadIdx.x;
    if (bx < PRO_X_BLKS) {
        int i = bx * 512 + tid;
#pragma unroll
        for (int u = 0; u < 2; u++) {
            float4 v = ((const float4*)x)[i + u * 256];
            ((__half2*)xh)[(i + u * 256) * 2]     = __floats2half2_rn(v.x, v.y);
            ((__half2*)xh)[(i + u * 256) * 2 + 1] = __floats2half2_rn(v.z, v.w);
        }
        return;
    }
    int t = bx - PRO_X_BLKS;
    const float* W; __half* Wt; int K, N; float scale; int gx, gy;
    if (t < 256)        { W = Wq; Wt = wtf;           K = Ed;  N = Ed;  scale = 1.0f;   gx = t % 16;          gy = t / 16; }
    else if (t < 512)   { W = Wk; Wt = wtf + 262144;  K = Ed;  N = Ed;  scale = 0.125f; gx = (t - 256) % 16;  gy = (t - 256) / 16; }
    else if (t < 1024)  { W = Wv; Wt = wtf + 524288;  K = Ed;  N = E2d; scale = 1.0f;   gx = (t - 512) % 32;  gy = (t - 512) / 32; }
    else if (t < 1536)  { W = Wg; Wt = wtf + 1048576; K = Ed;  N = E2d; scale = 1.0f;   gx = (t - 1024) % 32; gy = (t - 1024) / 32; }
    else                { W = Wo; Wt = wto;           K = E2d; N = Ed;  scale = 1.0f;   gx = (t - 1536) % 16; gy = (t - 1536) / 16; }

    __shared__ float tsm[32][33];
    int n0 = gx * 32, k0 = gy * 32;
    int tx = tid & 31, ty = tid >> 5;
#pragma unroll
    for (int i = 0; i < 4; i++)
        tsm[ty + i * 8][tx] = W[(size_t)(k0 + ty + i * 8) * N + n0 + tx];
    __syncthreads();
#pragma unroll
    for (int i = 0; i < 4; i++)
        Wt[(size_t)(n0 + ty + i * 8) * K + k0 + tx] = __float2half_rn(tsm[tx][ty + i * 8] * scale);
}

// ================= GEMM core (128x128 tile, 2 CTAs/SM) ==========
#define STAGES 3
#define STG_BYTES 16384
#define GEMM_SMEM (STAGES * 2 * STG_BYTES)

#define GEMM_PREFETCH(kt, st, Kdim) do {                                       \
    int _k0 = (kt) * 64;                                                       \
    uint32_t _b = sbase + (st) * STG_BYTES;                                    \
    _Pragma("unroll")                                                          \
    for (int p = 0; p < 4; p++) {                                              \
        int row = p * 32 + ldrow;                                              \
        uint32_t sw = row * 128 + (((uint32_t)(kh * 2)) ^ ((row & 7) << 4));   \
        CP_ASYNC16(_b + sw, &A[(size_t)(rowBlk + row) * (Kdim) + _k0 + kh]);   \
        CP_ASYNC16(_b + BOFF + sw, &Bt[(size_t)(colBlk + row) * (Kdim) + _k0 + kh]); \
    }                                                                          \
    CP_COMMIT;                                                                 \
} while (0)

#define GEMM_MAINLOOP(Kdim) do {                                               \
    const int L = (Kdim) >> 6;                                                 \
    GEMM_PREFETCH(0, 0, Kdim);                                                 \
    GEMM_PREFETCH(1, 1, Kdim);                                                 \
    for (int kt = 0; kt < L; kt++) {                                           \
        CP_WAIT(STAGES - 2);                                                   \
        __syncthreads();                                                       \
        int nf = kt + STAGES - 1;                                              \
        if (nf < L) GEMM_PREFETCH(nf, nf % STAGES, Kdim);                      \
        int st = kt % STAGES;                                                  \
        uint32_t baA = sbase + st * STG_BYTES + offA;                          \
        uint32_t baB = sbase + st * STG_BYTES + BOFF + offB;                   \
        _Pragma("unroll")                                                      \
        for (int s = 0; s < 4; s++) {                                          \
            uint32_t af[4][4];                                                 \
            _Pragma("unroll")                                                  \
            for (int mi = 0; mi < 4; mi++)                                     \
                LDSM4(af[mi][0], af[mi][1], af[mi][2], af[mi][3],              \
                      (baA + mi * 2048) ^ (uint32_t)(s * 32));                 \
            uint32_t bf[8];                                                    \
            LDSM4(bf[0], bf[1], bf[2], bf[3], baB ^ (uint32_t)(s * 32));       \
            LDSM4(bf[4], bf[5], bf[6], bf[7], (baB + 2048) ^ (uint32_t)(s * 32)); \
            _Pragma("unroll")                                                  \
            for (int mi = 0; mi < 4; mi++)                                     \
                _Pragma("unroll")                                              \
                for (int ni = 0; ni < 4; ni++)                                 \
                    MMA_F16(acc[mi][ni], af[mi], bf[ni * 2], bf[ni * 2 + 1]);  \
        }                                                                      \
    }                                                                          \
} while (0)

#define GEMM_PROLOG                                                            \
    extern __shared__ float smemf[];                                           \
    uint32_t sbase = smem_u32(smemf);                                          \
    const uint32_t BOFF = STAGES * STG_BYTES;                                  \
    int tid = threadIdx.x;                                                     \
    int lane = tid & 31;                                                       \
    int w = tid >> 5;                                                          \
    int wm = w & 1;                                                            \
    int wn = w >> 1;                                                           \
    float acc[4][4][4];                                                        \
    _Pragma("unroll")                                                          \
    for (int mi = 0; mi < 4; mi++)                                             \
        _Pragma("unroll")                                                      \
        for (int ni = 0; ni < 4; ni++)                                         \
            _Pragma("unroll")                                                  \
            for (int r = 0; r < 4; r++) acc[mi][ni][r] = 0.f;                  \
    int ldrow = tid >> 3;                                                      \
    int kh = (tid & 7) * 8;                                                    \
    int rowA0 = wm * 64 + (lane & 15);                                         \
    uint32_t offA = rowA0 * 128 + (((lane >> 4) * 16) ^ ((rowA0 & 7) << 4));   \
    int nB0 = wn * 32 + (lane & 7) + ((lane & 16) ? 8 : 0);                    \
    uint32_t offB = nB0 * 128 + ((((lane >> 3) & 1) * 16) ^ ((nB0 & 7) << 4));

// ---------------- fused QKVG projection GEMM ----------------
__global__ __launch_bounds__(256) void qkvg_gemm(
    const __half* __restrict__ A, const __half* __restrict__ Bt,
    __half* __restrict__ qp, __half* __restrict__ kp,
    __half* __restrict__ vp, __half* __restrict__ gp,
    const float* __restrict__ sinp, const float* __restrict__ cosp)
{
    GEMM_PROLOG
    int rowBlk = blockIdx.y * 128;
    int colBlk = blockIdx.x * 128;

    GEMM_MAINLOOP(Ed);

    int cbk = blockIdx.x;
    __half* dst; int N2; int col0; bool rot;
    if (cbk < 4)       { dst = qp; N2 = Ed;  col0 = cbk * 128;        rot = true; }
    else if (cbk < 8)  { dst = kp; N2 = Ed;  col0 = (cbk - 4) * 128;  rot = true; }
    else if (cbk < 16) { dst = vp; N2 = E2d; col0 = (cbk - 8) * 128;  rot = false; }
    else               { dst = gp; N2 = E2d; col0 = (cbk - 16) * 128; rot = false; }

    int r0 = lane >> 2, cp = (lane & 3) * 2;
#pragma unroll
    for (int mi = 0; mi < 4; mi++) {
#pragma unroll
        for (int ni = 0; ni < 4; ni++) {
            size_t row = (size_t)(rowBlk + wm * 64 + mi * 16 + r0);
            int col = col0 + wn * 32 + ni * 8 + cp;
            float o0 = acc[mi][ni][0], o1 = acc[mi][ni][1];
            float o2 = acc[mi][ni][2], o3 = acc[mi][ni][3];
            if (rot) {
                int t = (int)(row % Tl);
                int d = col & 63;
                float2 sl = *(const float2*)&sinp[t * KDd + d];
                float2 cl = *(const float2*)&cosp[t * KDd + d];
                float2 sh = *(const float2*)&sinp[(t + 8) * KDd + d];
                float2 ch = *(const float2*)&cosp[(t + 8) * KDd + d];
                float n0 = o0 * cl.x - o1 * sl.x;
                float n1 = o1 * cl.y + o0 * sl.y;
                float n2 = o2 * ch.x - o3 * sh.x;
                float n3 = o3 * ch.y + o2 * sh.y;
                o0 = n0; o1 = n1; o2 = n2; o3 = n3;
            }
            *(__half2*)&dst[row * N2 + col] = __floats2half2_rn(o0, o1);
            *(__half2*)&dst[(row + 8) * N2 + col] = __floats2half2_rn(o2, o3);
        }
    }
}

// ---------------- output projection GEMM (fp32 out) ----------------
__global__ __launch_bounds__(256) void out_gemm(
    const __half* __restrict__ A, const __half* __restrict__ Bt,
    float* __restrict__ C)
{
    GEMM_PROLOG
    int rowBlk = blockIdx.y * 128;
    int colBlk = blockIdx.x * 128;

    GEMM_MAINLOOP(E2d);

    int r0 = lane >> 2, cp = (lane & 3) * 2;
#pragma unroll
    for (int mi = 0; mi < 4; mi++) {
#pragma unroll
        for (int ni = 0; ni < 4; ni++) {
            size_t row = (size_t)(rowBlk + wm * 64 + mi * 16 + r0);
            int col = colBlk + wn * 32 + ni * 8 + cp;
            float2 w0 = {acc[mi][ni][0], acc[mi][ni][1]};
            float2 w1 = {acc[mi][ni][2], acc[mi][ni][3]};
            *(float2*)&C[row * Ed + col] = w0;
            *(float2*)&C[(row + 8) * Ed + col] = w1;
        }
    }
}

// ---------------- kv per chunk (fp16 TC; vid folded into kr; V cp.async db) --
#define LDAh 72
#define LDVh 136
#define VBUFB (64 * LDVh * 2)
__global__ __launch_bounds__(256) void kv_kernel(const __half* __restrict__ k,
                                                 const __half* __restrict__ v,
                                                 const float* __restrict__ vid,
                                                 float* __restrict__ kv)
{
    __shared__ __half kr_s[64 * LDAh];
    __shared__ __half v_s[2 * 64 * LDVh];
    int bx = blockIdx.x;
    int h = bx % Hd;
    int n = (bx / Hd) % NCd;
    int b = bx / (Hd * NCd);
    int tid = threadIdx.x;
    int lane = tid & 31;
    int w = tid >> 5;
    int wm3 = w & 3;
    int wn3 = w >> 2;
    int qrow = lane >> 2, qcol = lane & 3;
    int j = lane >> 3, rr = lane & 7;
    uint32_t skr = smem_u32(kr_s), svv = smem_u32(v_s);
    int arow_off = rr + ((j >> 1) << 3);
    int acol = wm3 * 16 + ((j & 1) << 3);
    int brow_off = rr + ((j & 1) << 3);
    int bcol_off = (j >> 1) << 3;
    long row0 = (long)b * Tl + n * Cd;

#define KV_PREF_V(ccx, bf) do {                                                \
    int _row = tid >> 2;                                                       \
    int _ec = (tid & 3) * 32;                                                  \
    uint32_t _vd = svv + (uint32_t)(bf) * VBUFB + (uint32_t)(_row * LDVh + _ec) * 2; \
    const __half* _vsrc = &v[(row0 + (ccx) * 64 + _row) * E2d + h * HDd + _ec];\
    CP_ASYNC16(_vd, _vsrc);      CP_ASYNC16(_vd + 16, _vsrc + 8);              \
    CP_ASYNC16(_vd + 32, _vsrc + 16); CP_ASYNC16(_vd + 48, _vsrc + 24);        \
    CP_COMMIT;                                                                 \
} while (0)

    float acc[8][4];
#pragma unroll
    for (int ni = 0; ni < 8; ni++)
#pragma unroll
        for (int r = 0; r < 4; r++) acc[ni][r] = 0.f;

    KV_PREF_V(0, 0);
    for (int cc = 0; cc < 4; cc++) {
        int buf = cc & 1;
        CP_WAIT(0);
        __syncthreads();
        if (cc < 3) KV_PREF_V(cc + 1, buf ^ 1);
        {   // stage kr scaled by vid (row = c index)
            int kg = (tid & 3) * 16, row = tid >> 2;
            float vvf = vid[h * Cd + cc * 64 + row];
            __half2 vvh = __floats2half2_rn(vvf, vvf);
            const uint4* ks_ = (const uint4*)&k[(row0 + cc * 64 + row) * Ed + h * KDd + kg];
            uint4 a0 = ks_[0], a1 = ks_[1];
            __half2* p0 = (__half2*)&a0;
            __half2* p1 = (__half2*)&a1;
#pragma unroll
            for (int i = 0; i < 4; i++) { p0[i] = __hmul2(p0[i], vvh); p1[i] = __hmul2(p1[i], vvh); }
            *(uint4*)&kr_s[row * LDAh + kg] = a0;
            *(uint4*)&kr_s[row * LDAh + kg + 8] = a1;
        }
        __syncthreads();
        uint32_t svb = svv + buf * VBUFB;
#pragma unroll
        for (int ks = 0; ks < 4; ks++) {
            uint32_t a[4];
            LDSM4T(a[0], a[1], a[2], a[3],
                   skr + (uint32_t)(((ks * 16 + arow_off) * LDAh + acol) * 2));
#pragma unroll
            for (int eb = 0; eb < 4; eb++) {
                uint32_t b0, b1, b2, b3;
                LDSM4T(b0, b1, b2, b3,
                       svb + (uint32_t)(((ks * 16 + brow_off) * LDVh + wn3 * 64 + eb * 16 + bcol_off) * 2));
                MMA_F16(acc[eb * 2], a, b0, b1);
                MMA_F16(acc[eb * 2 + 1], a, b2, b3);
            }
        }
    }
#undef KV_PREF_V

    float* outp = kv + (size_t)bx * (KDd * HDd);
    int r = wm3 * 16 + qrow;
#pragma unroll
    for (int ni = 0; ni < 8; ni++) {
        int e = wn3 * 64 + ni * 8 + 2 * qcol;
        float2 o0 = {acc[ni][0], acc[ni][1]};
        float2 o1 = {acc[ni][2], acc[ni][3]};
        *(float2*)&outp[r * HDd + e] = o0;
        *(float2*)&outp[(r + 8) * HDd + e] = o1;
    }
}

// ---------------- scan (float2 per thread) ----------------
__global__ void scan_kernel(const float2* __restrict__ kv,
                            const float* __restrict__ cd,
                            float2* __restrict__ state)
{
    int idx = blockIdx.x * 256 + threadIdx.x;
    const int EQ = KDd * HDd / 2;
    int e2 = idx % EQ;
    int bh = idx / EQ;
    int h = bh % Hd, b = bh / Hd;
    float c = cd[h];
    float2 s = {0.f, 0.f};
    for (int n = 0; n < NCd; n++) {
        size_t off = ((size_t)((b * NCd + n) * Hd + h)) * EQ + e2;
        state[off] = s;
        float2 kvv = kv[off];
        s.x = s.x * c + kvv.x;
        s.y = s.y * c + kvv.y;
    }
}

// ---------------- cross_scale ----------------
__global__ void cscale_kernel(const float* __restrict__ state, float* __restrict__ cs)
{
    int bx = blockIdx.x;
    int e = threadIdx.x;
    const float* sp = state + (size_t)bx * (KDd * HDd);
    float s = 0.f;
#pragma unroll 8
    for (int k2 = 0; k2 < KDd; k2++) s += fabsf(sp[k2 * HDd + e]);
#pragma unroll
    for (int o = 16; o > 0; o >>= 1) s = fmaxf(s, __shfl_xor_sync(0xffffffff, s, o));
    __shared__ float wmax[4];
    if ((e & 31) == 0) wmax[e >> 5] = s;
    __syncthreads();
    if (e == 0) {
        float m = fmaxf(fmaxf(wmax[0], wmax[1]), fmaxf(wmax[2], wmax[3]));
        cs[bx] = fmaxf(m, 1.0f);
    }
}

// ---------------- fp16 TC fused attention; cp.async double-buffered kr/V -----
#define KBUFB (64 * LDAh * 2)
#define ATTN_SMEM ((2 * 64 * LDAh + 2 * 64 * LDAh + 2 * 64 * LDVh) * 2 + (128 + 128 + 64) * 4)
__global__ __launch_bounds__(256) void attn_kernel(
    const __half* __restrict__ q, const __half* __restrict__ k,
    const __half* __restrict__ v, const __half* __restrict__ g,
    const float* __restrict__ state, const float* __restrict__ cs,
    const float* __restrict__ mask, const float* __restrict__ qid,
    __half* __restrict__ act)
{
    extern __shared__ char smraw[];
    __half* qr_s = (__half*)smraw;              // 64*72
    __half* qk_s = qr_s + 64 * LDAh;            // 64*72
    __half* kr_s = qk_s + 64 * LDAh;            // 2 x 64*72
    __half* v_s  = kr_s + 2 * 64 * LDAh;        // 2 x 64*136
    float* ipart = (float*)(v_s + 2 * 64 * LDVh);
    float* rpart = ipart + 128;
    float* qid_s = rpart + 128;

    int bx = blockIdx.x;
    int cb = bx % 4;
    int h  = (bx / 4) % Hd;
    int n  = (bx / (4 * Hd)) % NCd;
    int b  = bx / (4 * Hd * NCd);
    int tid = threadIdx.x;
    int lane = tid & 31;
    int w = tid >> 5;
    int wm = w >> 1;
    int wn = w & 1;
    int qrow = lane >> 2, qcol = lane & 3;
    int j = lane >> 3, rr = lane & 7;
    int clr = wm * 16 + qrow;
    uint32_t skr = smem_u32(kr_s);
    uint32_t sv = smem_u32(v_s);
    int vrow_off = rr + ((j & 1) << 3);
    int vcol_off = (j >> 1) << 3;
    long row0 = (long)b * Tl + n * Cd;

#define ATTN_PREF(dcx, bf) do {                                                \
    int _row = tid >> 2;                                                       \
    int _kg = (tid & 3) * 16;                                                  \
    uint32_t _kd = skr + (uint32_t)(bf) * KBUFB + (uint32_t)(_row * LDAh + _kg) * 2; \
    const __half* _ksrc = &k[(row0 + (dcx) * 64 + _row) * Ed + h * KDd + _kg]; \
    CP_ASYNC16(_kd, _ksrc);                                                    \
    CP_ASYNC16(_kd + 16, _ksrc + 8);                                           \
    int _ec = (tid & 3) * 32;                                                  \
    uint32_t _vd = sv + (uint32_t)(bf) * VBUFB + (uint32_t)(_row * LDVh + _ec) * 2; \
    const __half* _vsrc = &v[(row0 + (dcx) * 64 + _row) * E2d + h * HDd + _ec];\
    CP_ASYNC16(_vd, _vsrc);      CP_ASYNC16(_vd + 16, _vsrc + 8);              \
    CP_ASYNC16(_vd + 32, _vsrc + 16); CP_ASYNC16(_vd + 48, _vsrc + 24);        \
    CP_COMMIT;                                                                 \
} while (0)

    {
        int kg = (tid & 3) * 16, row = tid >> 2;
        const uint4* src = (const uint4*)&q[(row0 + cb * 64 + row) * Ed + h * KDd + kg];
        *(uint4*)&qr_s[row * LDAh + kg] = src[0];
        *(uint4*)&qr_s[row * LDAh + kg + 8] = src[1];
        if (tid < 64) qid_s[tid] = qid[h * Cd + cb * 64 + tid];
    }
    ATTN_PREF(0, 0);

    const float* mrow = mask + ((size_t)h * Cd + cb * 64) * Cd;
    float rs_lo = 0.f, rs_hi = 0.f;
    float acc2[8][4];
#pragma unroll
    for (int ni = 0; ni < 8; ni++)
#pragma unroll
        for (int r = 0; r < 4; r++) acc2[ni][r] = 0.f;

    for (int dc = 0; dc <= cb; dc++) {   // causal skip
        int buf = dc & 1;
        CP_WAIT(0);
        __syncthreads();
        if (dc < cb) ATTN_PREF(dc + 1, buf ^ 1);
        const __half* krb = kr_s + buf * (64 * LDAh);
        uint32_t svb = sv + buf * VBUFB;

        // qk = qr @ kr^T (warp: 16 rows x 32 keys, K=64)
        float acc1[4][4];
#pragma unroll
        for (int ni = 0; ni < 4; ni++)
#pragma unroll
            for (int r = 0; r < 4; r++) acc1[ni][r] = 0.f;
#pragma unroll
        for (int ks = 0; ks < 4; ks++) {
            int kk = ks * 16 + 2 * qcol;
            uint32_t a[4];
            a[0] = *(const uint32_t*)&qr_s[clr * LDAh + kk];
            a[1] = *(const uint32_t*)&qr_s[(clr + 8) * LDAh + kk];
            a[2] = *(const uint32_t*)&qr_s[clr * LDAh + kk + 8];
            a[3] = *(const uint32_t*)&qr_s[(clr + 8) * LDAh + kk + 8];
#pragma unroll
            for (int ni = 0; ni < 4; ni++) {
                int br = wn * 32 + ni * 8 + qrow;
                uint32_t b0 = *(const uint32_t*)&krb[br * LDAh + kk];
                uint32_t b1 = *(const uint32_t*)&krb[br * LDAh + kk + 8];
                MMA_F16(acc1[ni], a, b0, b1);
            }
        }

        // mask, |.| row-sum, stage masked qk as fp16
#pragma unroll
        for (int ni = 0; ni < 4; ni++) {
            int dl = wn * 32 + ni * 8 + 2 * qcol;
            int d = dc * 64 + dl;
            float2 mlo = *(const float2*)&mrow[(size_t)clr * Cd + d];
            float2 mhi = *(const float2*)&mrow[(size_t)(clr + 8) * Cd + d];
            acc1[ni][0] *= mlo.x; acc1[ni][1] *= mlo.y;
            acc1[ni][2] *= mhi.x; acc1[ni][3] *= mhi.y;
            rs_lo += fabsf(acc1[ni][0]) + fabsf(acc1[ni][1]);
            rs_hi += fabsf(acc1[ni][2]) + fabsf(acc1[ni][3]);
            *(__half2*)&qk_s[clr * LDAh + dl] = __floats2half2_rn(acc1[ni][0], acc1[ni][1]);
            *(__half2*)&qk_s[(clr + 8) * LDAh + dl] = __floats2half2_rn(acc1[ni][2], acc1[ni][3]);
        }
        __syncthreads();

        // PV: acc2 += qk[16x64] @ V[64 x 128-half]
#pragma unroll
        for (int ks = 0; ks < 4; ks++) {
            int kk = ks * 16 + 2 * qcol;
            uint32_t a[4];
            a[0] = *(const uint32_t*)&qk_s[clr * LDAh + kk];
            a[1] = *(const uint32_t*)&qk_s[(clr + 8) * LDAh + kk];
            a[2] = *(const uint32_t*)&qk_s[clr * LDAh + kk + 8];
            a[3] = *(const uint32_t*)&qk_s[(clr + 8) * LDAh + kk + 8];
#pragma unroll
            for (int eb = 0; eb < 4; eb++) {
                int e0 = wn * 64 + eb * 16;
                uint32_t b0, b1, b2, b3;
                LDSM4T(b0, b1, b2, b3,
                       svb + (uint32_t)(((ks * 16 + vrow_off) * LDVh + e0 + vcol_off) * 2));
                MMA_F16(acc2[eb * 2], a, b0, b1);
                MMA_F16(acc2[eb * 2 + 1], a, b2, b3);
            }
        }
    }
#undef ATTN_PREF

    // cross: stage state (fp32 -> fp16) into v_s buffer 0, then qr @ state
    __syncthreads();
    {
        const float* sp = state + ((size_t)((b * NCd + n) * Hd + h)) * (KDd * HDd);
        int row = tid >> 2, col = (tid & 3) * 32;
        const float4* sp4 = (const float4*)&sp[row * HDd + col];
#pragma unroll
        for (int i = 0; i < 8; i++) {
            float4 a4 = sp4[i];
            *(__half2*)&v_s[row * LDVh + col + i * 4]     = __floats2half2_rn(a4.x, a4.y);
            *(__half2*)&v_s[row * LDVh + col + i * 4 + 2] = __floats2half2_rn(a4.z, a4.w);
        }
    }
    __syncthreads();

    float acc3[8][4];
#pragma unroll
    for (int ni = 0; ni < 8; ni++)
#pragma unroll
        for (int r = 0; r < 4; r++) acc3[ni][r] = 0.f;
#pragma unroll
    for (int ks = 0; ks < 4; ks++) {
        int kk = ks * 16 + 2 * qcol;
        uint32_t a[4];
        a[0] = *(const uint32_t*)&qr_s[clr * LDAh + kk];
        a[1] = *(const uint32_t*)&qr_s[(clr + 8) * LDAh + kk];
        a[2] = *(const uint32_t*)&qr_s[clr * LDAh + kk + 8];
        a[3] = *(const uint32_t*)&qr_s[(clr + 8) * LDAh + kk + 8];
#pragma unroll
        for (int eb = 0; eb < 4; eb++) {
            int e0 = wn * 64 + eb * 16;
            uint32_t b0, b1, b2, b3;
            LDSM4T(b0, b1, b2, b3,
                   sv + (uint32_t)(((ks * 16 + vrow_off) * LDVh + e0 + vcol_off) * 2));
            MMA_F16(acc3[eb * 2], a, b0, b1);
            MMA_F16(acc3[eb * 2 + 1], a, b2, b3);
        }
    }

    rs_lo += __shfl_xor_sync(0xffffffff, rs_lo, 1);
    rs_lo += __shfl_xor_sync(0xffffffff, rs_lo, 2);
    rs_hi += __shfl_xor_sync(0xffffffff, rs_hi, 1);
    rs_hi += __shfl_xor_sync(0xffffffff, rs_hi, 2);
    if ((lane & 3) == 0) {
        ipart[wn * 64 + clr] = rs_lo;
        ipart[wn * 64 + clr + 8] = rs_hi;
    }
    __syncthreads();

    float csc = cs[(b * NCd + n) * Hd + h];
    float is_lo = fmaxf(1.f, ipart[clr] + ipart[64 + clr]);
    float is_hi = fmaxf(1.f, ipart[clr + 8] + ipart[64 + clr + 8]);
    float inv_lo = 1.f / fmaxf(is_lo, csc);
    float inv_hi = 1.f / fmaxf(is_hi, csc);
    float qd_lo = qid_s[clr], qd_hi = qid_s[clr + 8];

    float ss_lo = 0.f, ss_hi = 0.f;
#pragma unroll
    for (int ni = 0; ni < 8; ni++) {
        acc2[ni][0] = (acc2[ni][0] + qd_lo * acc3[ni][0]) * inv_lo;
        acc2[ni][1] = (acc2[ni][1] + qd_lo * acc3[ni][1]) * inv_lo;
        acc2[ni][2] = (acc2[ni][2] + qd_hi * acc3[ni][2]) * inv_hi;
        acc2[ni][3] = (acc2[ni][3] + qd_hi * acc3[ni][3]) * inv_hi;
        ss_lo += acc2[ni][0] * acc2[ni][0] + acc2[ni][1] * acc2[ni][1];
        ss_hi += acc2[ni][2] * acc2[ni][2] + acc2[ni][3] * acc2[ni][3];
    }
    ss_lo += __shfl_xor_sync(0xffffffff, ss_lo, 1);
    ss_lo += __shfl_xor_sync(0xffffffff, ss_lo, 2);
    ss_hi += __shfl_xor_sync(0xffffffff, ss_hi, 1);
    ss_hi += __shfl_xor_sync(0xffffffff, ss_hi, 2);
    if ((lane & 3) == 0) {
        rpart[wn * 64 + clr] = ss_lo;
        rpart[wn * 64 + clr + 8] = ss_hi;
    }
    __syncthreads();

    float rn_lo = rsqrtf((rpart[clr] + rpart[64 + clr]) * (1.f / 128.f) + 1e-6f);
    float rn_hi = rsqrtf((rpart[clr + 8] + rpart[64 + clr + 8]) * (1.f / 128.f) + 1e-6f);

    long grow_lo = row0 + cb * 64 + clr;
    long grow_hi = grow_lo + 8;
#pragma unroll
    for (int ni = 0; ni < 8; ni++) {
        int e = wn * 64 + ni * 8 + 2 * qcol;
        float2 gl = __half22float2(*(const __half2*)&g[grow_lo * E2d + h * HDd + e]);
        float2 gh = __half22float2(*(const __half2*)&g[grow_hi * E2d + h * HDd + e]);
        float o0 = acc2[ni][0] * rn_lo * gl.x * __fdividef(1.f, 1.f + __expf(-gl.x));
        float o1 = acc2[ni][1] * rn_lo * gl.y * __fdividef(1.f, 1.f + __expf(-gl.y));
        float o2 = acc2[ni][2] * rn_hi * gh.x * __fdividef(1.f, 1.f + __expf(-gh.x));
        float o3 = acc2[ni][3] * rn_hi * gh.y * __fdividef(1.f, 1.f + __expf(-gh.y));
        *(__half2*)&act[grow_lo * E2d + h * HDd + e] = __floats2half2_rn(o0, o1);
        *(__half2*)&act[grow_hi * E2d + h * HDd + e] = __floats2half2_rn(o2, o3);
    }
}

// ---------------- host launch ----------------
extern "C" void kernel_launch(void* const* d_in, const int* in_sizes, int n_in,
                              void* d_out, int out_size)
{
    const float* x    = (const float*)d_in[0];
    const float* sinp = (const float*)d_in[1];
    const float* cosp = (const float*)d_in[2];
    const float* mask = (const float*)d_in[3];
    const float* cdec = (const float*)d_in[4];
    const float* qid  = (const float*)d_in[5];
    const float* vid  = (const float*)d_in[6];
    const float* Wq   = (const float*)d_in[7];
    const float* Wk   = (const float*)d_in[8];
    const float* Wv   = (const float*)d_in[9];
    const float* Wg   = (const float*)d_in[10];
    const float* Wo   = (const float*)d_in[11];
    float* out = (float*)d_out;

    float *p_kv, *p_state, *p_cs;
    __half *p_q, *p_k, *p_v, *p_g, *p_xh, *p_act, *p_wt;
    cudaGetSymbolAddress((void**)&p_q, g_q);
    cudaGetSymbolAddress((void**)&p_k, g_k);
    cudaGetSymbolAddress((void**)&p_v, g_v);
    cudaGetSymbolAddress((void**)&p_g, g_g);
    cudaGetSymbolAddress((void**)&p_act, g_act);
    cudaGetSymbolAddress((void**)&p_xh, g_xh);
    cudaGetSymbolAddress((void**)&p_kv, g_kv);
    cudaGetSymbolAddress((void**)&p_state, g_state);
    cudaGetSymbolAddress((void**)&p_cs, g_cscale);
    cudaGetSymbolAddress((void**)&p_wt, g_wt);

    __half* wtf = p_wt;
    __half* wto = p_wt + 1572864;

    cudaFuncSetAttribute(attn_kernel, cudaFuncAttributeMaxDynamicSharedMemorySize, ATTN_SMEM);
    cudaFuncSetAttribute(qkvg_gemm, cudaFuncAttributeMaxDynamicSharedMemorySize, GEMM_SMEM);
    cudaFuncSetAttribute(out_gemm, cudaFuncAttributeMaxDynamicSharedMemorySize, GEMM_SMEM);

    // fused prologue
    prologue_kernel<<<PRO_X_BLKS + 2048, 256>>>(x, p_xh, Wq, Wk, Wv, Wg, Wo, wtf, wto);

    // fused QKVG projection (rotary fused for q/k blocks)
    qkvg_gemm<<<dim3(24, 256), 256, GEMM_SMEM>>>(p_xh, wtf, p_q, p_k, p_v, p_g, sinp, cosp);

    // per-chunk kv (cp.async V), scan, cross scale
    kv_kernel<<<Bz * NCd * Hd, 256>>>(p_k, p_v, vid, p_kv);
    scan_kernel<<<(Bz * Hd * KDd * HDd / 2) / 256, 256>>>(
        (const float2*)p_kv, cdec, (float2*)p_state);
    cscale_kernel<<<Bz * NCd * Hd, 128>>>(p_state, p_cs);

    // fp16 tensor-core fused attention (causal skip + cp.async prefetch)
    attn_kernel<<<Bz * NCd * Hd * 4, 256, ATTN_SMEM>>>(
        p_q, p_k, p_v, p_g, p_state, p_cs, mask, qid, p_act);

    // output projection (fp32 out)
    out_gemm<<<dim3(4, 256), 256, GEMM_SMEM>>>(p_act, wto, out);
}

// round 17
// speedup vs baseline: 1.4660x; 1.0102x over previous
#include <cuda_runtime.h>
#include <cuda_fp16.h>
#include <math.h>
#include <stdint.h>

// Dims (fixed for this problem)
#define Bz    4
#define Tl    8192
#define Ed    512
#define Hd    8
#define KDd   64
#define HDd   128
#define Cd    256
#define NCd   32
#define E2d   1024
#define Mtot  32768   // B*T

// ---------------- scratch (device globals; no runtime alloc) ----------------
__device__ __half g_q[(size_t)Mtot * Ed];
__device__ __half g_k[(size_t)Mtot * Ed];
__device__ __half g_v[(size_t)Mtot * E2d];
__device__ __half g_g[(size_t)Mtot * E2d];
__device__ __half g_act[(size_t)Mtot * E2d];
__device__ __half g_xh[(size_t)Mtot * Ed];    // fp16 x
__device__ float  g_kv[(size_t)Bz * NCd * Hd * KDd * HDd];
__device__ float  g_state[(size_t)Bz * NCd * Hd * KDd * HDd];
__device__ float  g_cscale[Bz * NCd * Hd];
__device__ __half g_wt[2621440];   // fused [3072,512] + Wo [512,1024]

__device__ __forceinline__ uint32_t smem_u32(const void* p) {
    uint32_t a;
    asm("{ .reg .u64 t; cvta.to.shared.u64 t, %1; cvt.u32.u64 %0, t; }"
        : "=r"(a) : "l"(p));
    return a;
}

#define LDSM4(r0, r1, r2, r3, a)                                               \
    asm volatile("ldmatrix.sync.aligned.m8n8.x4.shared.b16 {%0,%1,%2,%3}, [%4];" \
                 : "=r"(r0), "=r"(r1), "=r"(r2), "=r"(r3) : "r"(a))

#define LDSM4T(r0, r1, r2, r3, a)                                              \
    asm volatile("ldmatrix.sync.aligned.m8n8.x4.trans.shared.b16 {%0,%1,%2,%3}, [%4];" \
                 : "=r"(r0), "=r"(r1), "=r"(r2), "=r"(r3) : "r"(a))

#define MMA_F16(c, a, b0, b1)                                                  \
    asm volatile("mma.sync.aligned.m16n8k16.row.col.f32.f16.f16.f32 "          \
                 "{%0,%1,%2,%3},{%4,%5,%6,%7},{%8,%9},{%0,%1,%2,%3};"          \
                 : "+f"((c)[0]), "+f"((c)[1]), "+f"((c)[2]), "+f"((c)[3])      \
                 : "r"((a)[0]), "r"((a)[1]), "r"((a)[2]), "r"((a)[3]),         \
                   "r"(b0), "r"(b1))

#define CP_ASYNC16(dst, src)                                                   \
    asm volatile("cp.async.cg.shared.global [%0], [%1], 16;"                   \
                 :: "r"(dst), "l"(src))
#define CP_COMMIT asm volatile("cp.async.commit_group;" ::: "memory")
#define CP_WAIT(n) asm volatile("cp.async.wait_group %0;" :: "n"(n) : "memory")

// ---------------- fused prologue: x->fp16 + all 5 weight transposes ----------
#define PRO_X_BLKS 8192
__global__ __launch_bounds__(256) void prologue_kernel(
    const float* __restrict__ x, __half* __restrict__ xh,
    const float* __restrict__ Wq, const float* __restrict__ Wk,
    const float* __restrict__ Wv, const float* __restrict__ Wg,
    const float* __restrict__ Wo, __half* __restrict__ wtf, __half* __restrict__ wto)
{
    int bx = blockIdx.x;
    int tid = threadIdx.x;
    if (bx < PRO_X_BLKS) {
        int i = bx * 512 + tid;
#pragma unroll
        for (int u = 0; u < 2; u++) {
            float4 v = ((const float4*)x)[i + u * 256];
            ((__half2*)xh)[(i + u * 256) * 2]     = __floats2half2_rn(v.x, v.y);
            ((__half2*)xh)[(i + u * 256) * 2 + 1] = __floats2half2_rn(v.z, v.w);
        }
        return;
    }
    int t = bx - PRO_X_BLKS;
    const float* W; __half* Wt; int K, N; float scale; int gx, gy;
    if (t < 256)        { W = Wq; Wt = wtf;           K = Ed;  N = Ed;  scale = 1.0f;   gx = t % 16;          gy = t / 16; }
    else if (t < 512)   { W = Wk; Wt = wtf + 262144;  K = Ed;  N = Ed;  scale = 0.125f; gx = (t - 256) % 16;  gy = (t - 256) / 16; }
    else if (t < 1024)  { W = Wv; Wt = wtf + 524288;  K = Ed;  N = E2d; scale = 1.0f;   gx = (t - 512) % 32;  gy = (t - 512) / 32; }
    else if (t < 1536)  { W = Wg; Wt = wtf + 1048576; K = Ed;  N = E2d; scale = 1.0f;   gx = (t - 1024) % 32; gy = (t - 1024) / 32; }
    else                { W = Wo; Wt = wto;           K = E2d; N = Ed;  scale = 1.0f;   gx = (t - 1536) % 16; gy = (t - 1536) / 16; }

    __shared__ float tsm[32][33];
    int n0 = gx * 32, k0 = gy * 32;
    int tx = tid & 31, ty = tid >> 5;
#pragma unroll
    for (int i = 0; i < 4; i++)
        tsm[ty + i * 8][tx] = W[(size_t)(k0 + ty + i * 8) * N + n0 + tx];
    __syncthreads();
#pragma unroll
    for (int i = 0; i < 4; i++)
        Wt[(size_t)(n0 + ty + i * 8) * K + k0 + tx] = __float2half_rn(tsm[tx][ty + i * 8] * scale);
}

// ================= GEMM core (128x128 tile, 2 CTAs/SM) ==========
#define STAGES 3
#define STG_BYTES 16384
#define GEMM_SMEM (STAGES * 2 * STG_BYTES)

#define GEMM_PREFETCH(kt, st, Kdim) do {                                       \
    int _k0 = (kt) * 64;                                                       \
    uint32_t _b = sbase + (st) * STG_BYTES;                                    \
    _Pragma("unroll")                                                          \
    for (int p = 0; p < 4; p++) {                                              \
        int row = p * 32 + ldrow;                                              \
        uint32_t sw = row * 128 + (((uint32_t)(kh * 2)) ^ ((row & 7) << 4));   \
        CP_ASYNC16(_b + sw, &A[(size_t)(rowBlk + row) * (Kdim) + _k0 + kh]);   \
        CP_ASYNC16(_b + BOFF + sw, &Bt[(size_t)(colBlk + row) * (Kdim) + _k0 + kh]); \
    }                                                                          \
    CP_COMMIT;                                                                 \
} while (0)

#define GEMM_MAINLOOP(Kdim) do {                                               \
    const int L = (Kdim) >> 6;                                                 \
    GEMM_PREFETCH(0, 0, Kdim);                                                 \
    GEMM_PREFETCH(1, 1, Kdim);                                                 \
    for (int kt = 0; kt < L; kt++) {                                           \
        CP_WAIT(STAGES - 2);                                                   \
        __syncthreads();                                                       \
        int nf = kt + STAGES - 1;                                              \
        if (nf < L) GEMM_PREFETCH(nf, nf % STAGES, Kdim);                      \
        int st = kt % STAGES;                                                  \
        uint32_t baA = sbase + st * STG_BYTES + offA;                          \
        uint32_t baB = sbase + st * STG_BYTES + BOFF + offB;                   \
        _Pragma("unroll")                                                      \
        for (int s = 0; s < 4; s++) {                                          \
            uint32_t af[4][4];                                                 \
            _Pragma("unroll")                                                  \
            for (int mi = 0; mi < 4; mi++)                                     \
                LDSM4(af[mi][0], af[mi][1], af[mi][2], af[mi][3],              \
                      (baA + mi * 2048) ^ (uint32_t)(s * 32));                 \
            uint32_t bf[8];                                                    \
            LDSM4(bf[0], bf[1], bf[2], bf[3], baB ^ (uint32_t)(s * 32));       \
            LDSM4(bf[4], bf[5], bf[6], bf[7], (baB + 2048) ^ (uint32_t)(s * 32)); \
            _Pragma("unroll")                                                  \
            for (int mi = 0; mi < 4; mi++)                                     \
                _Pragma("unroll")                                              \
                for (int ni = 0; ni < 4; ni++)                                 \
                    MMA_F16(acc[mi][ni], af[mi], bf[ni * 2], bf[ni * 2 + 1]);  \
        }                                                                      \
    }                                                                          \
} while (0)

#define GEMM_PROLOG                                                            \
    extern __shared__ float smemf[];                                           \
    uint32_t sbase = smem_u32(smemf);                                          \
    const uint32_t BOFF = STAGES * STG_BYTES;                                  \
    int tid = threadIdx.x;                                                     \
    int lane = tid & 31;                                                       \
    int w = tid >> 5;                                                          \
    int wm = w & 1;                                                            \
    int wn = w >> 1;                                                           \
    float acc[4][4][4];                                                        \
    _Pragma("unroll")                                                          \
    for (int mi = 0; mi < 4; mi++)                                             \
        _Pragma("unroll")                                                      \
        for (int ni = 0; ni < 4; ni++)                                         \
            _Pragma("unroll")                                                  \
            for (int r = 0; r < 4; r++) acc[mi][ni][r] = 0.f;                  \
    int ldrow = tid >> 3;                                                      \
    int kh = (tid & 7) * 8;                                                    \
    int rowA0 = wm * 64 + (lane & 15);                                         \
    uint32_t offA = rowA0 * 128 + (((lane >> 4) * 16) ^ ((rowA0 & 7) << 4));   \
    int nB0 = wn * 32 + (lane & 7) + ((lane & 16) ? 8 : 0);                    \
    uint32_t offB = nB0 * 128 + ((((lane >> 3) & 1) * 16) ^ ((nB0 & 7) << 4));

// ---------------- fused QKVG projection GEMM ----------------
__global__ __launch_bounds__(256) void qkvg_gemm(
    const __half* __restrict__ A, const __half* __restrict__ Bt,
    __half* __restrict__ qp, __half* __restrict__ kp,
    __half* __restrict__ vp, __half* __restrict__ gp,
    const float* __restrict__ sinp, const float* __restrict__ cosp)
{
    GEMM_PROLOG
    int rowBlk = blockIdx.y * 128;
    int colBlk = blockIdx.x * 128;

    GEMM_MAINLOOP(Ed);

    int cbk = blockIdx.x;
    __half* dst; int N2; int col0; bool rot;
    if (cbk < 4)       { dst = qp; N2 = Ed;  col0 = cbk * 128;        rot = true; }
    else if (cbk < 8)  { dst = kp; N2 = Ed;  col0 = (cbk - 4) * 128;  rot = true; }
    else if (cbk < 16) { dst = vp; N2 = E2d; col0 = (cbk - 8) * 128;  rot = false; }
    else               { dst = gp; N2 = E2d; col0 = (cbk - 16) * 128; rot = false; }

    int r0 = lane >> 2, cp = (lane & 3) * 2;
#pragma unroll
    for (int mi = 0; mi < 4; mi++) {
#pragma unroll
        for (int ni = 0; ni < 4; ni++) {
            size_t row = (size_t)(rowBlk + wm * 64 + mi * 16 + r0);
            int col = col0 + wn * 32 + ni * 8 + cp;
            float o0 = acc[mi][ni][0], o1 = acc[mi][ni][1];
            float o2 = acc[mi][ni][2], o3 = acc[mi][ni][3];
            if (rot) {
                int t = (int)(row % Tl);
                int d = col & 63;
                float2 sl = *(const float2*)&sinp[t * KDd + d];
                float2 cl = *(const float2*)&cosp[t * KDd + d];
                float2 sh = *(const float2*)&sinp[(t + 8) * KDd + d];
                float2 ch = *(const float2*)&cosp[(t + 8) * KDd + d];
                float n0 = o0 * cl.x - o1 * sl.x;
                float n1 = o1 * cl.y + o0 * sl.y;
                float n2 = o2 * ch.x - o3 * sh.x;
                float n3 = o3 * ch.y + o2 * sh.y;
                o0 = n0; o1 = n1; o2 = n2; o3 = n3;
            }
            *(__half2*)&dst[row * N2 + col] = __floats2half2_rn(o0, o1);
            *(__half2*)&dst[(row + 8) * N2 + col] = __floats2half2_rn(o2, o3);
        }
    }
}

// ---------------- output projection GEMM (fp32 out) ----------------
__global__ __launch_bounds__(256) void out_gemm(
    const __half* __restrict__ A, const __half* __restrict__ Bt,
    float* __restrict__ C)
{
    GEMM_PROLOG
    int rowBlk = blockIdx.y * 128;
    int colBlk = blockIdx.x * 128;

    GEMM_MAINLOOP(E2d);

    int r0 = lane >> 2, cp = (lane & 3) * 2;
#pragma unroll
    for (int mi = 0; mi < 4; mi++) {
#pragma unroll
        for (int ni = 0; ni < 4; ni++) {
            size_t row = (size_t)(rowBlk + wm * 64 + mi * 16 + r0);
            int col = colBlk + wn * 32 + ni * 8 + cp;
            float2 w0 = {acc[mi][ni][0], acc[mi][ni][1]};
            float2 w1 = {acc[mi][ni][2], acc[mi][ni][3]};
            *(float2*)&C[row * Ed + col] = w0;
            *(float2*)&C[(row + 8) * Ed + col] = w1;
        }
    }
}

// ---------------- kv per chunk (fp16 TC; kr+V cp.async db; vid scaled in-smem)
#define LDAh 72
#define LDVh 136
#define VBUFB (64 * LDVh * 2)
#define KBUFB (64 * LDAh * 2)
__global__ __launch_bounds__(256) void kv_kernel(const __half* __restrict__ k,
                                                 const __half* __restrict__ v,
                                                 const float* __restrict__ vid,
                                                 float* __restrict__ kv)
{
    __shared__ __half kr_s[2 * 64 * LDAh];
    __shared__ __half v_s[2 * 64 * LDVh];
    __shared__ float vid_s[256];
    int bx = blockIdx.x;
    int h = bx % Hd;
    int n = (bx / Hd) % NCd;
    int b = bx / (Hd * NCd);
    int tid = threadIdx.x;
    int lane = tid & 31;
    int w = tid >> 5;
    int wm3 = w & 3;
    int wn3 = w >> 2;
    int qrow = lane >> 2, qcol = lane & 3;
    int j = lane >> 3, rr = lane & 7;
    uint32_t skr = smem_u32(kr_s), svv = smem_u32(v_s);
    int arow_off = rr + ((j >> 1) << 3);
    int acol = wm3 * 16 + ((j & 1) << 3);
    int brow_off = rr + ((j & 1) << 3);
    int bcol_off = (j >> 1) << 3;
    long row0 = (long)b * Tl + n * Cd;

#define KV_PREF(ccx, bf) do {                                                  \
    int _row = tid >> 2;                                                       \
    int _kg = (tid & 3) * 16;                                                  \
    uint32_t _kd = skr + (uint32_t)(bf) * KBUFB + (uint32_t)(_row * LDAh + _kg) * 2; \
    const __half* _ksrc = &k[(row0 + (ccx) * 64 + _row) * Ed + h * KDd + _kg]; \
    CP_ASYNC16(_kd, _ksrc);      CP_ASYNC16(_kd + 16, _ksrc + 8);              \
    int _ec = (tid & 3) * 32;                                                  \
    uint32_t _vd = svv + (uint32_t)(bf) * VBUFB + (uint32_t)(_row * LDVh + _ec) * 2; \
    const __half* _vsrc = &v[(row0 + (ccx) * 64 + _row) * E2d + h * HDd + _ec];\
    CP_ASYNC16(_vd, _vsrc);      CP_ASYNC16(_vd + 16, _vsrc + 8);              \
    CP_ASYNC16(_vd + 32, _vsrc + 16); CP_ASYNC16(_vd + 48, _vsrc + 24);        \
    CP_COMMIT;                                                                 \
} while (0)

    float acc[8][4];
#pragma unroll
    for (int ni = 0; ni < 8; ni++)
#pragma unroll
        for (int r = 0; r < 4; r++) acc[ni][r] = 0.f;

    vid_s[tid] = vid[h * Cd + tid];
    KV_PREF(0, 0);
    for (int cc = 0; cc < 4; cc++) {
        int buf = cc & 1;
        CP_WAIT(0);
        __syncthreads();
        if (cc < 3) KV_PREF(cc + 1, buf ^ 1);
        {   // scale kr in place by vid (row = c index); smem->smem, own region
            int kg = (tid & 3) * 16, row = tid >> 2;
            float vvf = vid_s[cc * 64 + row];
            __half2 vvh = __floats2half2_rn(vvf, vvf);
            __half* kp2 = &kr_s[buf * 64 * LDAh + row * LDAh + kg];
            uint4 a0 = *(uint4*)kp2;
            uint4 a1 = *(uint4*)(kp2 + 8);
            __half2* p0 = (__half2*)&a0;
            __half2* p1 = (__half2*)&a1;
#pragma unroll
            for (int i = 0; i < 4; i++) { p0[i] = __hmul2(p0[i], vvh); p1[i] = __hmul2(p1[i], vvh); }
            *(uint4*)kp2 = a0;
            *(uint4*)(kp2 + 8) = a1;
        }
        __syncthreads();
        uint32_t skb = skr + buf * KBUFB;
        uint32_t svb = svv + buf * VBUFB;
#pragma unroll
        for (int ks = 0; ks < 4; ks++) {
            uint32_t a[4];
            LDSM4T(a[0], a[1], a[2], a[3],
                   skb + (uint32_t)(((ks * 16 + arow_off) * LDAh + acol) * 2));
#pragma unroll
            for (int eb = 0; eb < 4; eb++) {
                uint32_t b0, b1, b2, b3;
                LDSM4T(b0, b1, b2, b3,
                       svb + (uint32_t)(((ks * 16 + brow_off) * LDVh + wn3 * 64 + eb * 16 + bcol_off) * 2));
                MMA_F16(acc[eb * 2], a, b0, b1);
                MMA_F16(acc[eb * 2 + 1], a, b2, b3);
            }
        }
    }
#undef KV_PREF

    float* outp = kv + (size_t)bx * (KDd * HDd);
    int r = wm3 * 16 + qrow;
#pragma unroll
    for (int ni = 0; ni < 8; ni++) {
        int e = wn3 * 64 + ni * 8 + 2 * qcol;
        float2 o0 = {acc[ni][0], acc[ni][1]};
        float2 o1 = {acc[ni][2], acc[ni][3]};
        *(float2*)&outp[r * HDd + e] = o0;
        *(float2*)&outp[(r + 8) * HDd + e] = o1;
    }
}

// ---------------- scan (float2 per thread) ----------------
__global__ void scan_kernel(const float2* __restrict__ kv,
                            const float* __restrict__ cd,
                            float2* __restrict__ state)
{
    int idx = blockIdx.x * 256 + threadIdx.x;
    const int EQ = KDd * HDd / 2;
    int e2 = idx % EQ;
    int bh = idx / EQ;
    int h = bh % Hd, b = bh / Hd;
    float c = cd[h];
    float2 s = {0.f, 0.f};
    for (int n = 0; n < NCd; n++) {
        size_t off = ((size_t)((b * NCd + n) * Hd + h)) * EQ + e2;
        state[off] = s;
        float2 kvv = kv[off];
        s.x = s.x * c + kvv.x;
        s.y = s.y * c + kvv.y;
    }
}

// ---------------- cross_scale ----------------
__global__ void cscale_kernel(const float* __restrict__ state, float* __restrict__ cs)
{
    int bx = blockIdx.x;
    int e = threadIdx.x;
    const float* sp = state + (size_t)bx * (KDd * HDd);
    float s = 0.f;
#pragma unroll 8
    for (int k2 = 0; k2 < KDd; k2++) s += fabsf(sp[k2 * HDd + e]);
#pragma unroll
    for (int o = 16; o > 0; o >>= 1) s = fmaxf(s, __shfl_xor_sync(0xffffffff, s, o));
    __shared__ float wmax[4];
    if ((e & 31) == 0) wmax[e >> 5] = s;
    __syncthreads();
    if (e == 0) {
        float m = fmaxf(fmaxf(wmax[0], wmax[1]), fmaxf(wmax[2], wmax[3]));
        cs[bx] = fmaxf(m, 1.0f);
    }
}

// ---------------- fp16 TC fused attention; cp.async kr/V + g smem prefetch ---
#define ATTN_SMEM ((2 * 64 * LDAh + 2 * 64 * LDAh + 2 * 64 * LDVh) * 2 + (128 + 128 + 64) * 4)
__global__ __launch_bounds__(256) void attn_kernel(
    const __half* __restrict__ q, const __half* __restrict__ k,
    const __half* __restrict__ v, const __half* __restrict__ g,
    const float* __restrict__ state, const float* __restrict__ cs,
    const float* __restrict__ mask, const float* __restrict__ qid,
    __half* __restrict__ act)
{
    extern __shared__ char smraw[];
    __half* qr_s = (__half*)smraw;              // 64*72
    __half* qk_s = qr_s + 64 * LDAh;            // 64*72
    __half* kr_s = qk_s + 64 * LDAh;            // 2 x 64*72 (reused as g buffer)
    __half* v_s  = kr_s + 2 * 64 * LDAh;        // 2 x 64*136
    float* ipart = (float*)(v_s + 2 * 64 * LDVh);
    float* rpart = ipart + 128;
    float* qid_s = rpart + 128;

    int bx = blockIdx.x;
    int cb = bx % 4;
    int h  = (bx / 4) % Hd;
    int n  = (bx / (4 * Hd)) % NCd;
    int b  = bx / (4 * Hd * NCd);
    int tid = threadIdx.x;
    int lane = tid & 31;
    int w = tid >> 5;
    int wm = w >> 1;
    int wn = w & 1;
    int qrow = lane >> 2, qcol = lane & 3;
    int j = lane >> 3, rr = lane & 7;
    int clr = wm * 16 + qrow;
    uint32_t skr = smem_u32(kr_s);
    uint32_t sv = smem_u32(v_s);
    int vrow_off = rr + ((j & 1) << 3);
    int vcol_off = (j >> 1) << 3;
    long row0 = (long)b * Tl + n * Cd;

#define ATTN_PREF(dcx, bf) do {                                                \
    int _row = tid >> 2;                                                       \
    int _kg = (tid & 3) * 16;                                                  \
    uint32_t _kd = skr + (uint32_t)(bf) * KBUFB + (uint32_t)(_row * LDAh + _kg) * 2; \
    const __half* _ksrc = &k[(row0 + (dcx) * 64 + _row) * Ed + h * KDd + _kg]; \
    CP_ASYNC16(_kd, _ksrc);                                                    \
    CP_ASYNC16(_kd + 16, _ksrc + 8);                                           \
    int _ec = (tid & 3) * 32;                                                  \
    uint32_t _vd = sv + (uint32_t)(bf) * VBUFB + (uint32_t)(_row * LDVh + _ec) * 2; \
    const __half* _vsrc = &v[(row0 + (dcx) * 64 + _row) * E2d + h * HDd + _ec];\
    CP_ASYNC16(_vd, _vsrc);      CP_ASYNC16(_vd + 16, _vsrc + 8);              \
    CP_ASYNC16(_vd + 32, _vsrc + 16); CP_ASYNC16(_vd + 48, _vsrc + 24);        \
    CP_COMMIT;                                                                 \
} while (0)

    {
        int kg = (tid & 3) * 16, row = tid >> 2;
        const uint4* src = (const uint4*)&q[(row0 + cb * 64 + row) * Ed + h * KDd + kg];
        *(uint4*)&qr_s[row * LDAh + kg] = src[0];
        *(uint4*)&qr_s[row * LDAh + kg + 8] = src[1];
        if (tid < 64) qid_s[tid] = qid[h * Cd + cb * 64 + tid];
    }
    ATTN_PREF(0, 0);

    const float* mrow = mask + ((size_t)h * Cd + cb * 64) * Cd;
    float rs_lo = 0.f, rs_hi = 0.f;
    float acc2[8][4];
#pragma unroll
    for (int ni = 0; ni < 8; ni++)
#pragma unroll
        for (int r = 0; r < 4; r++) acc2[ni][r] = 0.f;

    for (int dc = 0; dc <= cb; dc++) {   // causal skip
        int buf = dc & 1;
        CP_WAIT(0);
        __syncthreads();
        if (dc < cb) ATTN_PREF(dc + 1, buf ^ 1);
        const __half* krb = kr_s + buf * (64 * LDAh);
        uint32_t svb = sv + buf * VBUFB;

        // qk = qr @ kr^T (warp: 16 rows x 32 keys, K=64)
        float acc1[4][4];
#pragma unroll
        for (int ni = 0; ni < 4; ni++)
#pragma unroll
            for (int r = 0; r < 4; r++) acc1[ni][r] = 0.f;
#pragma unroll
        for (int ks = 0; ks < 4; ks++) {
            int kk = ks * 16 + 2 * qcol;
            uint32_t a[4];
            a[0] = *(const uint32_t*)&qr_s[clr * LDAh + kk];
            a[1] = *(const uint32_t*)&qr_s[(clr + 8) * LDAh + kk];
            a[2] = *(const uint32_t*)&qr_s[clr * LDAh + kk + 8];
            a[3] = *(const uint32_t*)&qr_s[(clr + 8) * LDAh + kk + 8];
#pragma unroll
            for (int ni = 0; ni < 4; ni++) {
                int br = wn * 32 + ni * 8 + qrow;
                uint32_t b0 = *(const uint32_t*)&krb[br * LDAh + kk];
                uint32_t b1 = *(const uint32_t*)&krb[br * LDAh + kk + 8];
                MMA_F16(acc1[ni], a, b0, b1);
            }
        }

        // mask, |.| row-sum, stage masked qk as fp16
#pragma unroll
        for (int ni = 0; ni < 4; ni++) {
            int dl = wn * 32 + ni * 8 + 2 * qcol;
            int d = dc * 64 + dl;
            float2 mlo = *(const float2*)&mrow[(size_t)clr * Cd + d];
            float2 mhi = *(const float2*)&mrow[(size_t)(clr + 8) * Cd + d];
            acc1[ni][0] *= mlo.x; acc1[ni][1] *= mlo.y;
            acc1[ni][2] *= mhi.x; acc1[ni][3] *= mhi.y;
            rs_lo += fabsf(acc1[ni][0]) + fabsf(acc1[ni][1]);
            rs_hi += fabsf(acc1[ni][2]) + fabsf(acc1[ni][3]);
            *(__half2*)&qk_s[clr * LDAh + dl] = __floats2half2_rn(acc1[ni][0], acc1[ni][1]);
            *(__half2*)&qk_s[(clr + 8) * LDAh + dl] = __floats2half2_rn(acc1[ni][2], acc1[ni][3]);
        }
        __syncthreads();

        // PV: acc2 += qk[16x64] @ V[64 x 128-half]
#pragma unroll
        for (int ks = 0; ks < 4; ks++) {
            int kk = ks * 16 + 2 * qcol;
            uint32_t a[4];
            a[0] = *(const uint32_t*)&qk_s[clr * LDAh + kk];
            a[1] = *(const uint32_t*)&qk_s[(clr + 8) * LDAh + kk];
            a[2] = *(const uint32_t*)&qk_s[clr * LDAh + kk + 8];
            a[3] = *(const uint32_t*)&qk_s[(clr + 8) * LDAh + kk + 8];
#pragma unroll
            for (int eb = 0; eb < 4; eb++) {
                int e0 = wn * 64 + eb * 16;
                uint32_t b0, b1, b2, b3;
                LDSM4T(b0, b1, b2, b3,
                       svb + (uint32_t)(((ks * 16 + vrow_off) * LDVh + e0 + vcol_off) * 2));
                MMA_F16(acc2[eb * 2], a, b0, b1);
                MMA_F16(acc2[eb * 2 + 1], a, b2, b3);
            }
        }
    }
#undef ATTN_PREF

    // mainloop done (all cp.async groups drained by in-loop CP_WAIT(0)).
    // kr_s is dead from here: prefetch the g tile into it (stride 136 halves,
    // 16B-aligned rows) to overlap with state staging + cross MMA + reductions.
    __syncthreads();
    {
        int row = tid >> 2, ec = (tid & 3) * 32;
        uint32_t gd = skr + (uint32_t)(row * 136 + ec) * 2;
        const __half* gsrc = &g[(row0 + cb * 64 + row) * E2d + h * HDd + ec];
        CP_ASYNC16(gd, gsrc);      CP_ASYNC16(gd + 16, gsrc + 8);
        CP_ASYNC16(gd + 32, gsrc + 16); CP_ASYNC16(gd + 48, gsrc + 24);
        CP_COMMIT;
    }
    // cross: stage state (fp32 -> fp16) into v_s buffer 0, then qr @ state
    {
        const float* sp = state + ((size_t)((b * NCd + n) * Hd + h)) * (KDd * HDd);
        int row = tid >> 2, col = (tid & 3) * 32;
        const float4* sp4 = (const float4*)&sp[row * HDd + col];
#pragma unroll
        for (int i = 0; i < 8; i++) {
            float4 a4 = sp4[i];
            *(__half2*)&v_s[row * LDVh + col + i * 4]     = __floats2half2_rn(a4.x, a4.y);
            *(__half2*)&v_s[row * LDVh + col + i * 4 + 2] = __floats2half2_rn(a4.z, a4.w);
        }
    }
    __syncthreads();

    float acc3[8][4];
#pragma unroll
    for (int ni = 0; ni < 8; ni++)
#pragma unroll
        for (int r = 0; r < 4; r++) acc3[ni][r] = 0.f;
#pragma unroll
    for (int ks = 0; ks < 4; ks++) {
        int kk = ks * 16 + 2 * qcol;
        uint32_t a[4];
        a[0] = *(const uint32_t*)&qr_s[clr * LDAh + kk];
        a[1] = *(const uint32_t*)&qr_s[(clr + 8) * LDAh + kk];
        a[2] = *(const uint32_t*)&qr_s[clr * LDAh + kk + 8];
        a[3] = *(const uint32_t*)&qr_s[(clr + 8) * LDAh + kk + 8];
#pragma unroll
        for (int eb = 0; eb < 4; eb++) {
            int e0 = wn * 64 + eb * 16;
            uint32_t b0, b1, b2, b3;
            LDSM4T(b0, b1, b2, b3,
                   sv + (uint32_t)(((ks * 16 + vrow_off) * LDVh + e0 + vcol_off) * 2));
            MMA_F16(acc3[eb * 2], a, b0, b1);
            MMA_F16(acc3[eb * 2 + 1], a, b2, b3);
        }
    }

    rs_lo += __shfl_xor_sync(0xffffffff, rs_lo, 1);
    rs_lo += __shfl_xor_sync(0xffffffff, rs_lo, 2);
    rs_hi += __shfl_xor_sync(0xffffffff, rs_hi, 1);
    rs_hi += __shfl_xor_sync(0xffffffff, rs_hi, 2);
    if ((lane & 3) == 0) {
        ipart[wn * 64 + clr] = rs_lo;
        ipart[wn * 64 + clr + 8] = rs_hi;
    }
    CP_WAIT(0);   // g tile landed; visibility at next barrier
    __syncthreads();

    float csc = cs[(b * NCd + n) * Hd + h];
    float is_lo = fmaxf(1.f, ipart[clr] + ipart[64 + clr]);
    float is_hi = fmaxf(1.f, ipart[clr + 8] + ipart[64 + clr + 8]);
    float inv_lo = 1.f / fmaxf(is_lo, csc);
    float inv_hi = 1.f / fmaxf(is_hi, csc);
    float qd_lo = qid_s[clr], qd_hi = qid_s[clr + 8];

    float ss_lo = 0.f, ss_hi = 0.f;
#pragma unroll
    for (int ni = 0; ni < 8; ni++) {
        acc2[ni][0] = (acc2[ni][0] + qd_lo * acc3[ni][0]) * inv_lo;
        acc2[ni][1] = (acc2[ni][1] + qd_lo * acc3[ni][1]) * inv_lo;
        acc2[ni][2] = (acc2[ni][2] + qd_hi * acc3[ni][2]) * inv_hi;
        acc2[ni][3] = (acc2[ni][3] + qd_hi * acc3[ni][3]) * inv_hi;
        ss_lo += acc2[ni][0] * acc2[ni][0] + acc2[ni][1] * acc2[ni][1];
        ss_hi += acc2[ni][2] * acc2[ni][2] + acc2[ni][3] * acc2[ni][3];
    }
    ss_lo += __shfl_xor_sync(0xffffffff, ss_lo, 1);
    ss_lo += __shfl_xor_sync(0xffffffff, ss_lo, 2);
    ss_hi += __shfl_xor_sync(0xffffffff, ss_hi, 1);
    ss_hi += __shfl_xor_sync(0xffffffff, ss_hi, 2);
    if ((lane & 3) == 0) {
        rpart[wn * 64 + clr] = ss_lo;
        rpart[wn * 64 + clr + 8] = ss_hi;
    }
    __syncthreads();

    float rn_lo = rsqrtf((rpart[clr] + rpart[64 + clr]) * (1.f / 128.f) + 1e-6f);
    float rn_hi = rsqrtf((rpart[clr + 8] + rpart[64 + clr + 8]) * (1.f / 128.f) + 1e-6f);

    long grow_lo = row0 + cb * 64 + clr;
    long grow_hi = grow_lo + 8;
#pragma unroll
    for (int ni = 0; ni < 8; ni++) {
        int e = wn * 64 + ni * 8 + 2 * qcol;
        float2 gl = __half22float2(*(const __half2*)&kr_s[clr * 136 + e]);
        float2 gh = __half22float2(*(const __half2*)&kr_s[(clr + 8) * 136 + e]);
        float o0 = acc2[ni][0] * rn_lo * gl.x * __fdividef(1.f, 1.f + __expf(-gl.x));
        float o1 = acc2[ni][1] * rn_lo * gl.y * __fdividef(1.f, 1.f + __expf(-gl.y));
        float o2 = acc2[ni][2] * rn_hi * gh.x * __fdividef(1.f, 1.f + __expf(-gh.x));
        float o3 = acc2[ni][3] * rn_hi * gh.y * __fdividef(1.f, 1.f + __expf(-gh.y));
        *(__half2*)&act[grow_lo * E2d + h * HDd + e] = __floats2half2_rn(o0, o1);
        *(__half2*)&act[grow_hi * E2d + h * HDd + e] = __floats2half2_rn(o2, o3);
    }
}

// ---------------- host launch ----------------
extern "C" void kernel_launch(void* const* d_in, const int* in_sizes, int n_in,
                              void* d_out, int out_size)
{
    const float* x    = (const float*)d_in[0];
    const float* sinp = (const float*)d_in[1];
    const float* cosp = (const float*)d_in[2];
    const float* mask = (const float*)d_in[3];
    const float* cdec = (const float*)d_in[4];
    const float* qid  = (const float*)d_in[5];
    const float* vid  = (const float*)d_in[6];
    const float* Wq   = (const float*)d_in[7];
    const float* Wk   = (const float*)d_in[8];
    const float* Wv   = (const float*)d_in[9];
    const float* Wg   = (const float*)d_in[10];
    const float* Wo   = (const float*)d_in[11];
    float* out = (float*)d_out;

    float *p_kv, *p_state, *p_cs;
    __half *p_q, *p_k, *p_v, *p_g, *p_xh, *p_act, *p_wt;
    cudaGetSymbolAddress((void**)&p_q, g_q);
    cudaGetSymbolAddress((void**)&p_k, g_k);
    cudaGetSymbolAddress((void**)&p_v, g_v);
    cudaGetSymbolAddress((void**)&p_g, g_g);
    cudaGetSymbolAddress((void**)&p_act, g_act);
    cudaGetSymbolAddress((void**)&p_xh, g_xh);
    cudaGetSymbolAddress((void**)&p_kv, g_kv);
    cudaGetSymbolAddress((void**)&p_state, g_state);
    cudaGetSymbolAddress((void**)&p_cs, g_cscale);
    cudaGetSymbolAddress((void**)&p_wt, g_wt);

    __half* wtf = p_wt;
    __half* wto = p_wt + 1572864;

    cudaFuncSetAttribute(attn_kernel, cudaFuncAttributeMaxDynamicSharedMemorySize, ATTN_SMEM);
    cudaFuncSetAttribute(qkvg_gemm, cudaFuncAttributeMaxDynamicSharedMemorySize, GEMM_SMEM);
    cudaFuncSetAttribute(out_gemm, cudaFuncAttributeMaxDynamicSharedMemorySize, GEMM_SMEM);

    // fused prologue
    prologue_kernel<<<PRO_X_BLKS + 2048, 256>>>(x, p_xh, Wq, Wk, Wv, Wg, Wo, wtf, wto);

    // fused QKVG projection (rotary fused for q/k blocks)
    qkvg_gemm<<<dim3(24, 256), 256, GEMM_SMEM>>>(p_xh, wtf, p_q, p_k, p_v, p_g, sinp, cosp);

    // per-chunk kv (cp.async kr+V), scan, cross scale
    kv_kernel<<<Bz * NCd * Hd, 256>>>(p_k, p_v, vid, p_kv);
    scan_kernel<<<(Bz * Hd * KDd * HDd / 2) / 256, 256>>>(
        (const float2*)p_kv, cdec, (float2*)p_state);
    cscale_kernel<<<Bz * NCd * Hd, 128>>>(p_state, p_cs);

    // fp16 tensor-core fused attention (causal skip + cp.async prefetch + g smem)
    attn_kernel<<<Bz * NCd * Hd * 4, 256, ATTN_SMEM>>>(
        p_q, p_k, p_v, p_g, p_state, p_cs, mask, qid, p_act);

    // output projection (fp32 out)
    out_gemm<<<dim3(4, 256), 256, GEMM_SMEM>>>(p_act, wto, out);
}